// round 10
// baseline (speedup 1.0000x reference)
#include <cuda_runtime.h>
#include <cuda_bf16.h>
#include <stdint.h>

#define N_NODES 16384
#define FDIM    128
#define NCLS    40

#define BM 128
#define BK 64
#define KTILES (N_NODES / BK)   // 256
#define SLOTS 4

// Scratch (static device globals — no allocation allowed)
__device__ float         g_support[(size_t)N_NODES * FDIM];   // 8 MB
__device__ __nv_bfloat16 g_featb [(size_t)N_NODES * FDIM];    // 4 MB

__device__ __forceinline__ uint32_t smaddr(const void* p) {
    return (uint32_t)__cvta_generic_to_shared(p);
}
__device__ __forceinline__ void mbar_init(uint32_t a, uint32_t cnt) {
    asm volatile("mbarrier.init.shared.b64 [%0], %1;" :: "r"(a), "r"(cnt) : "memory");
}
__device__ __forceinline__ void mbar_arrive(uint32_t a) {
    asm volatile("mbarrier.arrive.release.cta.shared.b64 _, [%0];" :: "r"(a) : "memory");
}
// Blocks while the barrier's phase == parity.
__device__ __forceinline__ void mbar_wait(uint32_t a, uint32_t parity) {
    uint32_t done;
    asm volatile(
        "{\n\t.reg .pred p;\n\t"
        "mbarrier.try_wait.parity.acquire.cta.shared::cta.b64 p, [%1], %2;\n\t"
        "selp.b32 %0, 1, 0, p;\n\t}"
        : "=r"(done) : "r"(a), "r"(parity) : "memory");
    if (!done) {
        asm volatile(
            "{\n\t.reg .pred P1;\n\t"
            "WAIT_LOOP_%=:\n\t"
            "mbarrier.try_wait.parity.acquire.cta.shared::cta.b64 P1, [%0], %1, 0x989680;\n\t"
            "@P1 bra.uni WAIT_DONE_%=;\n\t"
            "bra.uni WAIT_LOOP_%=;\n\t"
            "WAIT_DONE_%=:\n\t}"
            :: "r"(a), "r"(parity) : "memory");
    }
}

// ---------------------------------------------------------------------------
// Convert x (fp32) -> g_featb (bf16)
// ---------------------------------------------------------------------------
__global__ void cvt_x_kernel(const float* __restrict__ in) {
    int i = blockIdx.x * blockDim.x + threadIdx.x;
    int stride = gridDim.x * blockDim.x;
    const int n4 = N_NODES * FDIM / 4;
    const float4* in4 = (const float4*)in;
    __nv_bfloat162* ob = (__nv_bfloat162*)g_featb;
    for (; i < n4; i += stride) {
        float4 v = in4[i];
        ob[2 * i]     = __float22bfloat162_rn(make_float2(v.x, v.y));
        ob[2 * i + 1] = __float22bfloat162_rn(make_float2(v.z, v.w));
    }
}

// ---------------------------------------------------------------------------
// SpMM: g_support[N,128] = adj(fp32, cvt bf16 by producers) @ g_featb[N,128]
// Warp-specialized, CTA tile 128(M) x 128(N), BK=64, 384 threads, grid 128.
//  warps 0-3 : consumers, 2x2 grid of 64x64 tiles (one warp per SMSP).
//  warps 4-11: producers. A: LDG.128 fp32 (streaming, 2-deep reg staging)
//              -> cvt bf16 -> SW128 STS.  B: cp.async.cg bf16 (L2-hot).
// 4-slot mbarrier ring, 32KB/slot = 128KB smem, occ 1.
// ---------------------------------------------------------------------------
__global__ void __launch_bounds__(384, 1)
spmm_kernel(const float* __restrict__ A) {
    extern __shared__ char smem[];
    char* As = smem;                         // SLOTS * 16384 (128x64 bf16)
    char* Bs = smem + SLOTS * 16384;         // SLOTS * 16384 (64x128 bf16)
    __shared__ uint64_t bar_full[SLOTS];
    __shared__ uint64_t bar_empty[SLOTS];
    const uint32_t as0 = smaddr(As);
    const uint32_t bs0 = smaddr(Bs);
    const uint32_t bf_ = smaddr(&bar_full[0]);
    const uint32_t be_ = smaddr(&bar_empty[0]);

    const int t    = threadIdx.x;
    const int lane = t & 31;
    const int warp = t >> 5;
    const int m0 = blockIdx.x * BM;

    if (t == 0) {
        #pragma unroll
        for (int s = 0; s < SLOTS; ++s) {
            mbar_init(bf_ + s * 8, 256);   // producer threads arrive
            mbar_init(be_ + s * 8, 128);   // consumer threads arrive
        }
    }
    __syncthreads();

    if (warp >= 4) {
        // ===================== PRODUCERS (warps 4-11, 256 thr) =============
        const int pt = t - 128;            // 0..255
        const int ar = pt >> 4;            // 0..15
        const int af = pt & 15;            // 16B fp32 chunk within 64-float row
        const float* Abase = A + (size_t)m0 * N_NODES;
        float4 rA[8], rB[8];

        auto ldgA = [&](int kt, float4 (&rg)[8]) {
            const float* src = Abase + (size_t)kt * BK + af * 4;
            #pragma unroll
            for (int p = 0; p < 8; ++p)
                rg[p] = __ldcs((const float4*)(src + (size_t)(p * 16 + ar) * N_NODES));
        };
        auto stsA = [&](int slot, const float4 (&rg)[8]) {
            char* dst = As + slot * 16384;
            const int c = af >> 1, h = af & 1;
            #pragma unroll
            for (int p = 0; p < 8; ++p) {
                int r = p * 16 + ar;
                int off = r * 128 + (((c ^ (r & 7)) << 4) | (h << 3));
                __nv_bfloat162 lo = __float22bfloat162_rn(make_float2(rg[p].x, rg[p].y));
                __nv_bfloat162 hi = __float22bfloat162_rn(make_float2(rg[p].z, rg[p].w));
                uint2 v; v.x = *(uint32_t*)&lo; v.y = *(uint32_t*)&hi;
                *(uint2*)(dst + off) = v;
            }
        };
        auto cpB = [&](int kt, int slot) {
            const char* gsrc = (const char*)(g_featb + (size_t)kt * BK * FDIM);
            const uint32_t sbase = bs0 + slot * 16384;
            #pragma unroll
            for (int p = 0; p < 4; ++p) {
                int idx = pt + p * 256;     // 0..1023
                int r = idx >> 4;           // k-node row 0..63
                int c = idx & 15;
                uint32_t soff = r * 256 + ((c ^ ((r & 7) << 1)) << 4);
                asm volatile("cp.async.cg.shared.global [%0], [%1], 16;\n"
                             :: "r"(sbase + soff), "l"(gsrc + (size_t)r * 256 + c * 16));
            }
        };

        // prologue: tile 0 into flight
        mbar_wait(be_ + 0, 1);             // empty[0] -> immediate
        cpB(0, 0);
        asm volatile("cp.async.commit_group;\n");
        ldgA(0, rA);

        #pragma unroll 1
        for (int tt = 0; tt < KTILES; tt += 2) {
            { // even tile tt (data in rA), prefetch tt+1 into rB
                const int nt = tt + 1;
                const int ns = nt & (SLOTS - 1);
                mbar_wait(be_ + ns * 8, ((nt >> 2) & 1) ^ 1);
                cpB(nt, ns);
                asm volatile("cp.async.commit_group;\n");
                ldgA(nt, rB);
                stsA(tt & (SLOTS - 1), rA);
                asm volatile("cp.async.wait_group 1;\n");
                mbar_arrive(bf_ + (tt & (SLOTS - 1)) * 8);
            }
            { // odd tile tt+1 (data in rB), prefetch tt+2 into rA
                const int ct = tt + 1, nt = tt + 2;
                if (nt < KTILES) {
                    const int ns = nt & (SLOTS - 1);
                    mbar_wait(be_ + ns * 8, ((nt >> 2) & 1) ^ 1);
                    cpB(nt, ns);
                    asm volatile("cp.async.commit_group;\n");
                    ldgA(nt, rA);
                    stsA(ct & (SLOTS - 1), rB);
                    asm volatile("cp.async.wait_group 1;\n");
                } else {
                    stsA(ct & (SLOTS - 1), rB);
                    asm volatile("cp.async.wait_group 0;\n");
                }
                mbar_arrive(bf_ + (ct & (SLOTS - 1)) * 8);
            }
        }
    } else {
        // ===================== CONSUMERS (warps 0-3) =======================
        const int wm = warp & 1;       // 0..1, M half (64 rows each)
        const int wn = warp >> 1;      // 0..1, N half (64 cols each)

        float acc[4][8][4];
        #pragma unroll
        for (int i = 0; i < 4; ++i)
            #pragma unroll
            for (int j = 0; j < 8; ++j)
                #pragma unroll
                for (int k = 0; k < 4; ++k) acc[i][j][k] = 0.f;

        #pragma unroll 1
        for (int tt = 0; tt < KTILES; ++tt) {
            const int slot = tt & (SLOTS - 1);
            mbar_wait(bf_ + slot * 8, (tt >> 2) & 1);
            const uint32_t ab = as0 + slot * 16384;
            const uint32_t bb = bs0 + slot * 16384;
            #pragma unroll
            for (int ks = 0; ks < 4; ++ks) {
                uint32_t a[4][4];
                #pragma unroll
                for (int mt = 0; mt < 4; ++mt) {
                    int r = wm * 64 + mt * 16 + (lane & 15);
                    int c = ks * 2 + (lane >> 4);
                    uint32_t addr = ab + r * 128 + ((c ^ (r & 7)) << 4);
                    asm volatile("ldmatrix.sync.aligned.m8n8.x4.shared.b16 {%0,%1,%2,%3}, [%4];\n"
                        : "=r"(a[mt][0]), "=r"(a[mt][1]), "=r"(a[mt][2]), "=r"(a[mt][3])
                        : "r"(addr));
                }
                #pragma unroll
                for (int nt = 0; nt < 8; ++nt) {
                    uint32_t b0, b1;
                    int r = ks * 16 + (lane & 15);
                    int c = wn * 8 + nt;
                    uint32_t addr = bb + r * 256 + ((c ^ ((r & 7) << 1)) << 4);
                    asm volatile("ldmatrix.sync.aligned.m8n8.x2.trans.shared.b16 {%0,%1}, [%2];\n"
                        : "=r"(b0), "=r"(b1) : "r"(addr));
                    #pragma unroll
                    for (int mt = 0; mt < 4; ++mt) {
                        asm volatile(
                            "mma.sync.aligned.m16n8k16.row.col.f32.bf16.bf16.f32 "
                            "{%0,%1,%2,%3}, {%4,%5,%6,%7}, {%8,%9}, {%0,%1,%2,%3};\n"
                            : "+f"(acc[mt][nt][0]), "+f"(acc[mt][nt][1]),
                              "+f"(acc[mt][nt][2]), "+f"(acc[mt][nt][3])
                            : "r"(a[mt][0]), "r"(a[mt][1]), "r"(a[mt][2]), "r"(a[mt][3]),
                              "r"(b0), "r"(b1));
                    }
                }
            }
            mbar_arrive(be_ + slot * 8);
        }

        // Epilogue: fragment -> g_support (fp32, row-major)
        float* Cp = g_support + (size_t)m0 * FDIM;
        #pragma unroll
        for (int mt = 0; mt < 4; ++mt) {
            int r0 = wm * 64 + mt * 16 + (lane >> 2);
            #pragma unroll
            for (int nt = 0; nt < 8; ++nt) {
                int c0 = wn * 64 + nt * 8 + (lane & 3) * 2;
                *(float2*)(Cp + (size_t)r0 * FDIM + c0)       = make_float2(acc[mt][nt][0], acc[mt][nt][1]);
                *(float2*)(Cp + (size_t)(r0 + 8) * FDIM + c0) = make_float2(acc[mt][nt][2], acc[mt][nt][3]);
            }
        }
    }
}

// ---------------------------------------------------------------------------
// h = relu( [X | g_support] @ W + b ), W is [256,128].
// Writes fp32 to `out`; optionally also bf16 to g_featb (input to next SpMM).
// ---------------------------------------------------------------------------
__global__ void __launch_bounds__(256)
sage_linear_kernel(const float* __restrict__ X,
                   const float* __restrict__ W,
                   const float* __restrict__ bias,
                   float* __restrict__ out,
                   int write_bf16) {
    __shared__ float INs[64][16];
    __shared__ float Ws[16][128];
    const int t  = threadIdx.x;
    const int tr = t >> 5;
    const int tc = t & 31;
    const int row0 = blockIdx.x * 64;

    float acc[8][4];
    #pragma unroll
    for (int i = 0; i < 8; ++i)
        #pragma unroll
        for (int j = 0; j < 4; ++j) acc[i][j] = 0.f;

    for (int kb = 0; kb < 16; ++kb) {
        const int kbase = kb * 16;
        #pragma unroll
        for (int j = 0; j < 4; ++j) {
            int idx = t + j * 256;
            int r = idx >> 4, kk = idx & 15;
            int k = kbase + kk;
            float v;
            if (k < FDIM) v = X[(size_t)(row0 + r) * FDIM + k];
            else          v = g_support[(size_t)(row0 + r) * FDIM + (k - FDIM)];
            INs[r][kk] = v;
        }
        #pragma unroll
        for (int j = 0; j < 8; ++j) {
            int idx = t + j * 256;
            int wr = idx >> 7, wc = idx & 127;
            Ws[wr][wc] = W[(size_t)(kbase + wr) * FDIM + wc];
        }
        __syncthreads();
        #pragma unroll
        for (int kk = 0; kk < 16; ++kk) {
            float4 w = *(const float4*)&Ws[kk][tc * 4];
            #pragma unroll
            for (int i = 0; i < 8; ++i) {
                float xv = INs[tr * 8 + i][kk];
                acc[i][0] = fmaf(xv, w.x, acc[i][0]);
                acc[i][1] = fmaf(xv, w.y, acc[i][1]);
                acc[i][2] = fmaf(xv, w.z, acc[i][2]);
                acc[i][3] = fmaf(xv, w.w, acc[i][3]);
            }
        }
        __syncthreads();
    }

    const float4 bv = *(const float4*)&bias[tc * 4];
    #pragma unroll
    for (int i = 0; i < 8; ++i) {
        int r = row0 + tr * 8 + i;
        float4 o;
        o.x = fmaxf(acc[i][0] + bv.x, 0.f);
        o.y = fmaxf(acc[i][1] + bv.y, 0.f);
        o.z = fmaxf(acc[i][2] + bv.z, 0.f);
        o.w = fmaxf(acc[i][3] + bv.w, 0.f);
        *(float4*)&out[(size_t)r * FDIM + tc * 4] = o;
        if (write_bf16) {
            __nv_bfloat162 lo = __float22bfloat162_rn(make_float2(o.x, o.y));
            __nv_bfloat162 hi = __float22bfloat162_rn(make_float2(o.z, o.w));
            uint2 v;
            v.x = *(uint32_t*)&lo;
            v.y = *(uint32_t*)&hi;
            *(uint2*)&g_featb[(size_t)r * FDIM + tc * 4] = v;
        }
    }
}

// ---------------------------------------------------------------------------
// logits = h2 @ Wl + bl ; log_probs = logits - logsumexp(logits)
// ---------------------------------------------------------------------------
__global__ void __launch_bounds__(128)
classifier_kernel(const float* __restrict__ H,
                  const float* __restrict__ Wl,
                  const float* __restrict__ bl,
                  float* __restrict__ logp,
                  float* __restrict__ logits) {
    extern __shared__ float sh[];
    float* Hs  = sh;                  // 128*129
    float* Wls = sh + 128 * 129;      // 128*40
    float* bls = Wls + 128 * NCLS;    // 40
    const int t = threadIdx.x;
    const int row0 = blockIdx.x * 128;

    for (int j = 0; j < 128; ++j)
        Hs[j * 129 + t] = H[(size_t)(row0 + j) * FDIM + t];
    for (int idx = t; idx < 128 * NCLS; idx += 128)
        Wls[idx] = Wl[idx];
    if (t < NCLS) bls[t] = bl[t];
    __syncthreads();

    float acc[NCLS];
    #pragma unroll
    for (int c = 0; c < NCLS; ++c) acc[c] = bls[c];

    const float* hr = &Hs[t * 129];
    #pragma unroll 4
    for (int k = 0; k < FDIM; ++k) {
        float xv = hr[k];
        #pragma unroll
        for (int c = 0; c < NCLS; c += 4) {
            float4 w = *(const float4*)&Wls[k * NCLS + c];
            acc[c + 0] = fmaf(xv, w.x, acc[c + 0]);
            acc[c + 1] = fmaf(xv, w.y, acc[c + 1]);
            acc[c + 2] = fmaf(xv, w.z, acc[c + 2]);
            acc[c + 3] = fmaf(xv, w.w, acc[c + 3]);
        }
    }

    float m = acc[0];
    #pragma unroll
    for (int c = 1; c < NCLS; ++c) m = fmaxf(m, acc[c]);
    float s = 0.f;
    #pragma unroll
    for (int c = 0; c < NCLS; ++c) s += __expf(acc[c] - m);
    float lse = m + __logf(s);

    size_t ro = (size_t)(row0 + t) * NCLS;
    #pragma unroll
    for (int c = 0; c < NCLS; ++c) {
        logits[ro + c] = acc[c];
        logp[ro + c]   = acc[c] - lse;
    }
}

// ---------------------------------------------------------------------------
extern "C" void kernel_launch(void* const* d_in, const int* in_sizes, int n_in,
                              void* d_out, int out_size) {
    (void)in_sizes; (void)n_in; (void)out_size;
    const float* x   = (const float*)d_in[0];
    const float* adj = (const float*)d_in[1];
    const float* W1  = (const float*)d_in[2];
    const float* b1  = (const float*)d_in[3];
    const float* W2  = (const float*)d_in[4];
    const float* b2  = (const float*)d_in[5];
    const float* Wl  = (const float*)d_in[6];
    const float* bl  = (const float*)d_in[7];

    float* out    = (float*)d_out;
    float* logp   = out;                                  // [N, 40]
    float* h1     = logp + (size_t)N_NODES * NCLS;        // [N, 128]
    float* h2     = h1 + (size_t)N_NODES * FDIM;          // [N, 128]
    float* logits = h2 + (size_t)N_NODES * FDIM;          // [N, 40]

    const int cls_smem  = (128 * 129 + 128 * NCLS + NCLS) * (int)sizeof(float);
    const int spmm_smem = SLOTS * (16384 + 16384);   // 128 KB
    cudaFuncSetAttribute(spmm_kernel, cudaFuncAttributeMaxDynamicSharedMemorySize, spmm_smem);
    cudaFuncSetAttribute(classifier_kernel, cudaFuncAttributeMaxDynamicSharedMemorySize, cls_smem);

    // 1) x -> bf16
    cvt_x_kernel<<<512, 256>>>(x);
    // 2) support = adj @ x
    spmm_kernel<<<N_NODES / BM, 384, spmm_smem>>>(adj);
    // 3) h1 = relu([x|s]@W1 + b1)  (also emits bf16 h1 into g_featb)
    sage_linear_kernel<<<N_NODES / 64, 256>>>(x, W1, b1, h1, 1);
    // 4) support = adj @ h1
    spmm_kernel<<<N_NODES / BM, 384, spmm_smem>>>(adj);
    // 5) h2 = relu([h1|s]@W2 + b2)
    sage_linear_kernel<<<N_NODES / 64, 256>>>(h1, W2, b2, h2, 0);
    // 6) logits + log_softmax
    classifier_kernel<<<N_NODES / 128, 128, cls_smem>>>(h2, Wl, bl, logp, logits);
}

// round 12
// speedup vs baseline: 1.2344x; 1.2344x over previous
#include <cuda_runtime.h>
#include <cuda_bf16.h>
#include <stdint.h>

#define N_NODES 16384
#define FDIM    128
#define NCLS    40

#define BM 64
#define BK 64
#define KTILES (N_NODES / BK)   // 256
#define STAGES 4

// Scratch (static device globals — no allocation allowed)
__device__ float         g_support[(size_t)N_NODES * FDIM];   // 8 MB
__device__ __nv_bfloat16 g_featb [(size_t)N_NODES * FDIM];    // 4 MB

__device__ __forceinline__ uint32_t smaddr(const void* p) {
    return (uint32_t)__cvta_generic_to_shared(p);
}
__device__ __forceinline__ void mbar_init(uint32_t a, uint32_t cnt) {
    asm volatile("mbarrier.init.shared.b64 [%0], %1;" :: "r"(a), "r"(cnt) : "memory");
}
__device__ __forceinline__ void mbar_arrive(uint32_t a) {
    asm volatile("mbarrier.arrive.release.cta.shared.b64 _, [%0];" :: "r"(a) : "memory");
}
// Blocks while the barrier's phase == parity.
__device__ __forceinline__ void mbar_wait(uint32_t a, uint32_t parity) {
    uint32_t done;
    asm volatile(
        "{\n\t.reg .pred p;\n\t"
        "mbarrier.try_wait.parity.acquire.cta.shared::cta.b64 p, [%1], %2;\n\t"
        "selp.b32 %0, 1, 0, p;\n\t}"
        : "=r"(done) : "r"(a), "r"(parity) : "memory");
    if (!done) {
        asm volatile(
            "{\n\t.reg .pred P1;\n\t"
            "WAIT_LOOP_%=:\n\t"
            "mbarrier.try_wait.parity.acquire.cta.shared::cta.b64 P1, [%0], %1, 0x989680;\n\t"
            "@P1 bra.uni WAIT_DONE_%=;\n\t"
            "bra.uni WAIT_LOOP_%=;\n\t"
            "WAIT_DONE_%=:\n\t}"
            :: "r"(a), "r"(parity) : "memory");
    }
}

// ---------------------------------------------------------------------------
// Convert x (fp32) -> g_featb (bf16)
// ---------------------------------------------------------------------------
__global__ void cvt_x_kernel(const float* __restrict__ in) {
    int i = blockIdx.x * blockDim.x + threadIdx.x;
    int stride = gridDim.x * blockDim.x;
    const int n4 = N_NODES * FDIM / 4;
    const float4* in4 = (const float4*)in;
    __nv_bfloat162* ob = (__nv_bfloat162*)g_featb;
    for (; i < n4; i += stride) {
        float4 v = in4[i];
        ob[2 * i]     = __float22bfloat162_rn(make_float2(v.x, v.y));
        ob[2 * i + 1] = __float22bfloat162_rn(make_float2(v.z, v.w));
    }
}

// ---------------------------------------------------------------------------
// SpMM (R5-proven): g_support[N,128] = adj @ g_featb[N,128]
// Warp-specialized: warps 0-3 consume (ldmatrix+mma), warps 4-7 produce.
// CTA tile 64(M) x 128(N), BK=64, 4-stage mbarrier ring, occ 2, grid 256.
// ---------------------------------------------------------------------------
__global__ void __launch_bounds__(256, 2)
spmm_kernel(const float* __restrict__ A) {
    extern __shared__ char smem[];
    char* As = smem;                         // STAGES * 8192
    char* Bs = smem + STAGES * 8192;         // STAGES * 16384
    __shared__ uint64_t bar_full[STAGES];
    __shared__ uint64_t bar_empty[STAGES];
    const uint32_t as0 = smaddr(As);
    const uint32_t bs0 = smaddr(Bs);
    const uint32_t bf0 = smaddr(&bar_full[0]);
    const uint32_t be0 = smaddr(&bar_empty[0]);

    const int t    = threadIdx.x;
    const int lane = t & 31;
    const int warp = t >> 5;
    const int m0 = blockIdx.x * BM;

    if (t == 0) {
        #pragma unroll
        for (int s = 0; s < STAGES; ++s) {
            mbar_init(bf0 + s * 8, 128);   // producers arrive
            mbar_init(be0 + s * 8, 128);   // consumers arrive
        }
    }
    __syncthreads();

    if (warp >= 4) {
        // ===================== PRODUCER (warps 4-7) =====================
        const int pt = t - 128;            // 0..127
        const int ar = pt >> 4;            // 0..7
        const int af = pt & 15;            // float4 slot within 64-float row
        const float* Abase = A + (size_t)m0 * N_NODES;

        float4 regA[8], regB[8];

        auto ldgA = [&](int kt, float4 (&rg)[8]) {
            const float* src = Abase + (size_t)kt * BK + af * 4;
            #pragma unroll
            for (int p = 0; p < 8; ++p) {
                int r = p * 8 + ar;
                rg[p] = *(const float4*)(src + (size_t)r * N_NODES);
            }
        };
        auto stsA = [&](int slot, const float4 (&rg)[8]) {
            char* dst = As + slot * 8192;
            const int c = af >> 1, h = af & 1;
            #pragma unroll
            for (int p = 0; p < 8; ++p) {
                int r = p * 8 + ar;
                int off = r * 128 + (((c ^ (r & 7)) << 4) | (h << 3));
                __nv_bfloat162 lo = __float22bfloat162_rn(make_float2(rg[p].x, rg[p].y));
                __nv_bfloat162 hi = __float22bfloat162_rn(make_float2(rg[p].z, rg[p].w));
                uint2 v;
                v.x = *(uint32_t*)&lo;
                v.y = *(uint32_t*)&hi;
                *(uint2*)(dst + off) = v;
            }
        };
        auto cpB = [&](int kt, int slot) {
            const char* gsrc = (const char*)(g_featb + (size_t)kt * BK * FDIM);
            const uint32_t sbase = bs0 + slot * 16384;
            #pragma unroll
            for (int p = 0; p < 8; ++p) {
                int idx = pt + p * 128;     // 0..1023
                int r = idx >> 4;           // 0..63
                int c = idx & 15;
                uint32_t soff = r * 256 + ((c ^ ((r & 7) << 1)) << 4);
                asm volatile("cp.async.cg.shared.global [%0], [%1], 16;\n"
                             :: "r"(sbase + soff), "l"(gsrc + (size_t)r * 256 + c * 16));
            }
        };

        // prologue: tile 0 into flight
        mbar_wait(be0 + 0, 1);             // empty[0], parity 1 -> immediate
        cpB(0, 0);
        asm volatile("cp.async.commit_group;\n");
        ldgA(0, regA);

        #pragma unroll 1
        for (int tt = 0; tt < KTILES; tt += 2) {
            // ---- even tile tt (data in regA), prefetch tt+1 into regB
            {
                const int nt = tt + 1;
                const int ns = nt & (STAGES - 1);
                mbar_wait(be0 + ns * 8, ((nt >> 2) & 1) ^ 1);
                cpB(nt, ns);
                asm volatile("cp.async.commit_group;\n");
                ldgA(nt, regB);
                stsA(tt & (STAGES - 1), regA);
                asm volatile("cp.async.wait_group 1;\n");
                mbar_arrive(bf0 + (tt & (STAGES - 1)) * 8);
            }
            // ---- odd tile tt+1 (data in regB), prefetch tt+2 into regA
            {
                const int ct = tt + 1;
                const int nt = tt + 2;
                if (nt < KTILES) {
                    const int ns = nt & (STAGES - 1);
                    mbar_wait(be0 + ns * 8, ((nt >> 2) & 1) ^ 1);
                    cpB(nt, ns);
                    asm volatile("cp.async.commit_group;\n");
                    ldgA(nt, regA);
                    stsA(ct & (STAGES - 1), regB);
                    asm volatile("cp.async.wait_group 1;\n");
                } else {
                    stsA(ct & (STAGES - 1), regB);
                    asm volatile("cp.async.wait_group 0;\n");
                }
                mbar_arrive(bf0 + (ct & (STAGES - 1)) * 8);
            }
        }
    } else {
        // ===================== CONSUMER (warps 0-3) =====================
        const int wm = warp & 1;       // 0..1 (M groups of 32)
        const int wn = warp >> 1;      // 0..1 (N groups of 64)

        float acc[2][8][4];
        #pragma unroll
        for (int i = 0; i < 2; ++i)
            #pragma unroll
            for (int j = 0; j < 8; ++j)
                #pragma unroll
                for (int k = 0; k < 4; ++k) acc[i][j][k] = 0.f;

        #pragma unroll 1
        for (int tt = 0; tt < KTILES; ++tt) {
            const int slot = tt & (STAGES - 1);
            mbar_wait(bf0 + slot * 8, (tt >> 2) & 1);
            const uint32_t ab = as0 + slot * 8192;
            const uint32_t bb = bs0 + slot * 16384;
            #pragma unroll
            for (int ks = 0; ks < 4; ++ks) {
                uint32_t a[2][4];
                #pragma unroll
                for (int mt = 0; mt < 2; ++mt) {
                    int r = wm * 32 + mt * 16 + (lane & 15);
                    int c = ks * 2 + (lane >> 4);
                    uint32_t addr = ab + r * 128 + ((c ^ (r & 7)) << 4);
                    asm volatile("ldmatrix.sync.aligned.m8n8.x4.shared.b16 {%0,%1,%2,%3}, [%4];\n"
                        : "=r"(a[mt][0]), "=r"(a[mt][1]), "=r"(a[mt][2]), "=r"(a[mt][3])
                        : "r"(addr));
                }
                uint32_t b[8][2];
                #pragma unroll
                for (int nt = 0; nt < 8; ++nt) {
                    int r = ks * 16 + (lane & 15);
                    int c = wn * 8 + nt;
                    uint32_t addr = bb + r * 256 + ((c ^ ((r & 7) << 1)) << 4);
                    asm volatile("ldmatrix.sync.aligned.m8n8.x2.trans.shared.b16 {%0,%1}, [%2];\n"
                        : "=r"(b[nt][0]), "=r"(b[nt][1]) : "r"(addr));
                }
                #pragma unroll
                for (int mt = 0; mt < 2; ++mt)
                    #pragma unroll
                    for (int nt = 0; nt < 8; ++nt) {
                        asm volatile(
                            "mma.sync.aligned.m16n8k16.row.col.f32.bf16.bf16.f32 "
                            "{%0,%1,%2,%3}, {%4,%5,%6,%7}, {%8,%9}, {%0,%1,%2,%3};\n"
                            : "+f"(acc[mt][nt][0]), "+f"(acc[mt][nt][1]),
                              "+f"(acc[mt][nt][2]), "+f"(acc[mt][nt][3])
                            : "r"(a[mt][0]), "r"(a[mt][1]), "r"(a[mt][2]), "r"(a[mt][3]),
                              "r"(b[nt][0]), "r"(b[nt][1]));
                    }
            }
            mbar_arrive(be0 + slot * 8);
        }

        // Epilogue: fragment -> g_support (fp32, row-major)
        float* Cp = g_support + (size_t)m0 * FDIM;
        #pragma unroll
        for (int mt = 0; mt < 2; ++mt) {
            int r0 = wm * 32 + mt * 16 + (lane >> 2);
            #pragma unroll
            for (int nt = 0; nt < 8; ++nt) {
                int c0 = wn * 64 + nt * 8 + (lane & 3) * 2;
                *(float2*)(Cp + (size_t)r0 * FDIM + c0)       = make_float2(acc[mt][nt][0], acc[mt][nt][1]);
                *(float2*)(Cp + (size_t)(r0 + 8) * FDIM + c0) = make_float2(acc[mt][nt][2], acc[mt][nt][3]);
            }
        }
    }
}

// ---------------------------------------------------------------------------
// Tensor-core SAGE linear, bf16 hi/lo split (fp32-accurate):
//   h = relu([X | g_support] @ W + b)
// A (fp32 X rows, K 0-127) and g_support (K 128-255) are split into bf16
// hi+lo tiles; W likewise. Product = ahi*whi + alo*whi + ahi*wlo (fp32 acc):
// residual O(eps^2) ~ 1e-5. CTA 64 rows x 128 cols, 256 threads,
// warp grid 2(M) x 4(N), K=256 in two halves. smem 192KB, occ 1, grid 256.
// Writes fp32 `out`; optionally bf16 h into g_featb (X is read from fp32
// global, never from g_featb, so the overwrite is safe).
// ---------------------------------------------------------------------------
__global__ void __launch_bounds__(256)
sage_linear_tc(const float* __restrict__ X,
               const float* __restrict__ Wmat,
               const float* __restrict__ bias,
               float* __restrict__ out,
               int write_bf16) {
    extern __shared__ char sm[];
    // A tiles: [half][64 rows][128 bf16] swizzled 256B rows, 16KB each
    char* Ahi = sm;               // 2 * 16KB = 32KB
    char* Alo = sm + 32768;       // 2 * 16KB = 32KB
    // W tiles: [half][128 rows(k)][128 bf16] swizzled, 32KB each
    char* Whi = sm + 65536;       // 2 * 32KB = 64KB
    char* Wlo = sm + 131072;      // 2 * 32KB = 64KB
    const uint32_t ahi0 = smaddr(Ahi);
    const uint32_t alo0 = smaddr(Alo);
    const uint32_t whi0 = smaddr(Whi);
    const uint32_t wlo0 = smaddr(Wlo);

    const int t = threadIdx.x;
    const int lane = t & 31;
    const int warp = t >> 5;
    const int wm = warp & 1;       // 2 M groups of 32 rows
    const int wn = warp >> 1;      // 4 N groups of 32 cols
    const int m0 = blockIdx.x * 64;

    // Stage A halves (fp32 -> bf16 hi/lo, swizzled)
    #pragma unroll
    for (int half = 0; half < 2; ++half) {
        const float* src = half ? (g_support + (size_t)m0 * FDIM)
                                : (X + (size_t)m0 * FDIM);
        char* dhi = Ahi + half * 16384;
        char* dlo = Alo + half * 16384;
        #pragma unroll
        for (int p = 0; p < 8; ++p) {
            int idx = t + p * 256;          // 0..2047
            int r = idx >> 5, af = idx & 31;
            float4 v = *(const float4*)(src + (size_t)r * FDIM + af * 4);
            int c = af >> 1, h = af & 1;
            uint32_t off = r * 256 + (((c ^ ((r & 7) << 1)) << 4) | (h << 3));
            __nv_bfloat16 hx = __float2bfloat16(v.x), hy = __float2bfloat16(v.y);
            __nv_bfloat16 hz = __float2bfloat16(v.z), hw = __float2bfloat16(v.w);
            __nv_bfloat16 lx = __float2bfloat16(v.x - __bfloat162float(hx));
            __nv_bfloat16 ly = __float2bfloat16(v.y - __bfloat162float(hy));
            __nv_bfloat16 lz = __float2bfloat16(v.z - __bfloat162float(hz));
            __nv_bfloat16 lw = __float2bfloat16(v.w - __bfloat162float(hw));
            uint2 uh, ul;
            uh.x = ((uint32_t)*(uint16_t*)&hy << 16) | *(uint16_t*)&hx;
            uh.y = ((uint32_t)*(uint16_t*)&hw << 16) | *(uint16_t*)&hz;
            ul.x = ((uint32_t)*(uint16_t*)&ly << 16) | *(uint16_t*)&lx;
            ul.y = ((uint32_t)*(uint16_t*)&lw << 16) | *(uint16_t*)&lz;
            *(uint2*)(dhi + off) = uh;
            *(uint2*)(dlo + off) = ul;
        }
    }

    // Stage W halves (fp32 [256,128] -> bf16 hi/lo, swizzled; L2-hot)
    #pragma unroll
    for (int half = 0; half < 2; ++half) {
        char* dhi = Whi + half * 32768;
        char* dlo = Wlo + half * 32768;
        #pragma unroll 4
        for (int p = 0; p < 16; ++p) {
            int idx = t + p * 256;          // 0..4095
            int r = idx >> 5, af = idx & 31;
            float4 v = *(const float4*)(Wmat + (size_t)(half * 128 + r) * FDIM + af * 4);
            int c = af >> 1, h = af & 1;
            uint32_t off = r * 256 + (((c ^ ((r & 7) << 1)) << 4) | (h << 3));
            __nv_bfloat16 hx = __float2bfloat16(v.x), hy = __float2bfloat16(v.y);
            __nv_bfloat16 hz = __float2bfloat16(v.z), hw = __float2bfloat16(v.w);
            __nv_bfloat16 lx = __float2bfloat16(v.x - __bfloat162float(hx));
            __nv_bfloat16 ly = __float2bfloat16(v.y - __bfloat162float(hy));
            __nv_bfloat16 lz = __float2bfloat16(v.z - __bfloat162float(hz));
            __nv_bfloat16 lw = __float2bfloat16(v.w - __bfloat162float(hw));
            uint2 uh, ul;
            uh.x = ((uint32_t)*(uint16_t*)&hy << 16) | *(uint16_t*)&hx;
            uh.y = ((uint32_t)*(uint16_t*)&hw << 16) | *(uint16_t*)&hz;
            ul.x = ((uint32_t)*(uint16_t*)&ly << 16) | *(uint16_t*)&lx;
            ul.y = ((uint32_t)*(uint16_t*)&lw << 16) | *(uint16_t*)&lz;
            *(uint2*)(dhi + off) = uh;
            *(uint2*)(dlo + off) = ul;
        }
    }
    __syncthreads();

    float acc[2][4][4];
    #pragma unroll
    for (int i = 0; i < 2; ++i)
        #pragma unroll
        for (int j = 0; j < 4; ++j)
            #pragma unroll
            for (int k = 0; k < 4; ++k) acc[i][j][k] = 0.f;

    #pragma unroll
    for (int half = 0; half < 2; ++half) {
        const uint32_t abh = ahi0 + half * 16384;
        const uint32_t abl = alo0 + half * 16384;
        const uint32_t wbh = whi0 + half * 32768;
        const uint32_t wbl = wlo0 + half * 32768;
        #pragma unroll
        for (int ks = 0; ks < 8; ++ks) {
            uint32_t ah[2][4], al[2][4];
            #pragma unroll
            for (int mt = 0; mt < 2; ++mt) {
                int r = wm * 32 + mt * 16 + (lane & 15);
                int c = ks * 2 + (lane >> 4);
                uint32_t sw = r * 256 + ((c ^ ((r & 7) << 1)) << 4);
                asm volatile("ldmatrix.sync.aligned.m8n8.x4.shared.b16 {%0,%1,%2,%3}, [%4];\n"
                    : "=r"(ah[mt][0]), "=r"(ah[mt][1]), "=r"(ah[mt][2]), "=r"(ah[mt][3])
                    : "r"(abh + sw));
                asm volatile("ldmatrix.sync.aligned.m8n8.x4.shared.b16 {%0,%1,%2,%3}, [%4];\n"
                    : "=r"(al[mt][0]), "=r"(al[mt][1]), "=r"(al[mt][2]), "=r"(al[mt][3])
                    : "r"(abl + sw));
            }
            #pragma unroll
            for (int nt = 0; nt < 4; ++nt) {
                int r = ks * 16 + (lane & 15);
                int c = wn * 4 + nt;
                uint32_t sw = r * 256 + ((c ^ ((r & 7) << 1)) << 4);
                uint32_t bh0, bh1, bl0, bl1;
                asm volatile("ldmatrix.sync.aligned.m8n8.x2.trans.shared.b16 {%0,%1}, [%2];\n"
                    : "=r"(bh0), "=r"(bh1) : "r"(wbh + sw));
                asm volatile("ldmatrix.sync.aligned.m8n8.x2.trans.shared.b16 {%0,%1}, [%2];\n"
                    : "=r"(bl0), "=r"(bl1) : "r"(wbl + sw));
                #pragma unroll
                for (int mt = 0; mt < 2; ++mt) {
                    asm volatile(
                        "mma.sync.aligned.m16n8k16.row.col.f32.bf16.bf16.f32 "
                        "{%0,%1,%2,%3}, {%4,%5,%6,%7}, {%8,%9}, {%0,%1,%2,%3};\n"
                        : "+f"(acc[mt][nt][0]), "+f"(acc[mt][nt][1]),
                          "+f"(acc[mt][nt][2]), "+f"(acc[mt][nt][3])
                        : "r"(ah[mt][0]), "r"(ah[mt][1]), "r"(ah[mt][2]), "r"(ah[mt][3]),
                          "r"(bh0), "r"(bh1));
                    asm volatile(
                        "mma.sync.aligned.m16n8k16.row.col.f32.bf16.bf16.f32 "
                        "{%0,%1,%2,%3}, {%4,%5,%6,%7}, {%8,%9}, {%0,%1,%2,%3};\n"
                        : "+f"(acc[mt][nt][0]), "+f"(acc[mt][nt][1]),
                          "+f"(acc[mt][nt][2]), "+f"(acc[mt][nt][3])
                        : "r"(al[mt][0]), "r"(al[mt][1]), "r"(al[mt][2]), "r"(al[mt][3]),
                          "r"(bh0), "r"(bh1));
                    asm volatile(
                        "mma.sync.aligned.m16n8k16.row.col.f32.bf16.bf16.f32 "
                        "{%0,%1,%2,%3}, {%4,%5,%6,%7}, {%8,%9}, {%0,%1,%2,%3};\n"
                        : "+f"(acc[mt][nt][0]), "+f"(acc[mt][nt][1]),
                          "+f"(acc[mt][nt][2]), "+f"(acc[mt][nt][3])
                        : "r"(ah[mt][0]), "r"(ah[mt][1]), "r"(ah[mt][2]), "r"(ah[mt][3]),
                          "r"(bl0), "r"(bl1));
                }
            }
        }
    }

    // Epilogue: bias + relu -> fp32 out (+ optional bf16 g_featb)
    #pragma unroll
    for (int mt = 0; mt < 2; ++mt) {
        int r0 = m0 + wm * 32 + mt * 16 + (lane >> 2);
        #pragma unroll
        for (int nt = 0; nt < 4; ++nt) {
            int c0 = wn * 32 + nt * 8 + (lane & 3) * 2;
            float bv0 = __ldg(&bias[c0]);
            float bv1 = __ldg(&bias[c0 + 1]);
            float o00 = fmaxf(acc[mt][nt][0] + bv0, 0.f);
            float o01 = fmaxf(acc[mt][nt][1] + bv1, 0.f);
            float o10 = fmaxf(acc[mt][nt][2] + bv0, 0.f);
            float o11 = fmaxf(acc[mt][nt][3] + bv1, 0.f);
            *(float2*)(out + (size_t)r0 * FDIM + c0)       = make_float2(o00, o01);
            *(float2*)(out + (size_t)(r0 + 8) * FDIM + c0) = make_float2(o10, o11);
            if (write_bf16) {
                __nv_bfloat162 p0 = __float22bfloat162_rn(make_float2(o00, o01));
                __nv_bfloat162 p1 = __float22bfloat162_rn(make_float2(o10, o11));
                *(__nv_bfloat162*)(g_featb + (size_t)r0 * FDIM + c0)       = p0;
                *(__nv_bfloat162*)(g_featb + (size_t)(r0 + 8) * FDIM + c0) = p1;
            }
        }
    }
}

// ---------------------------------------------------------------------------
// logits = h2 @ Wl + bl ; log_probs = logits - logsumexp(logits)
// ---------------------------------------------------------------------------
__global__ void __launch_bounds__(128)
classifier_kernel(const float* __restrict__ H,
                  const float* __restrict__ Wl,
                  const float* __restrict__ bl,
                  float* __restrict__ logp,
                  float* __restrict__ logits) {
    extern __shared__ float sh[];
    float* Hs  = sh;                  // 128*129
    float* Wls = sh + 128 * 129;      // 128*40
    float* bls = Wls + 128 * NCLS;    // 40
    const int t = threadIdx.x;
    const int row0 = blockIdx.x * 128;

    for (int j = 0; j < 128; ++j)
        Hs[j * 129 + t] = H[(size_t)(row0 + j) * FDIM + t];
    for (int idx = t; idx < 128 * NCLS; idx += 128)
        Wls[idx] = Wl[idx];
    if (t < NCLS) bls[t] = bl[t];
    __syncthreads();

    float acc[NCLS];
    #pragma unroll
    for (int c = 0; c < NCLS; ++c) acc[c] = bls[c];

    const float* hr = &Hs[t * 129];
    #pragma unroll 4
    for (int k = 0; k < FDIM; ++k) {
        float xv = hr[k];
        #pragma unroll
        for (int c = 0; c < NCLS; c += 4) {
            float4 w = *(const float4*)&Wls[k * NCLS + c];
            acc[c + 0] = fmaf(xv, w.x, acc[c + 0]);
            acc[c + 1] = fmaf(xv, w.y, acc[c + 1]);
            acc[c + 2] = fmaf(xv, w.z, acc[c + 2]);
            acc[c + 3] = fmaf(xv, w.w, acc[c + 3]);
        }
    }

    float m = acc[0];
    #pragma unroll
    for (int c = 1; c < NCLS; ++c) m = fmaxf(m, acc[c]);
    float s = 0.f;
    #pragma unroll
    for (int c = 0; c < NCLS; ++c) s += __expf(acc[c] - m);
    float lse = m + __logf(s);

    size_t ro = (size_t)(row0 + t) * NCLS;
    #pragma unroll
    for (int c = 0; c < NCLS; ++c) {
        logits[ro + c] = acc[c];
        logp[ro + c]   = acc[c] - lse;
    }
}

// ---------------------------------------------------------------------------
extern "C" void kernel_launch(void* const* d_in, const int* in_sizes, int n_in,
                              void* d_out, int out_size) {
    (void)in_sizes; (void)n_in; (void)out_size;
    const float* x   = (const float*)d_in[0];
    const float* adj = (const float*)d_in[1];
    const float* W1  = (const float*)d_in[2];
    const float* b1  = (const float*)d_in[3];
    const float* W2  = (const float*)d_in[4];
    const float* b2  = (const float*)d_in[5];
    const float* Wl  = (const float*)d_in[6];
    const float* bl  = (const float*)d_in[7];

    float* out    = (float*)d_out;
    float* logp   = out;                                  // [N, 40]
    float* h1     = logp + (size_t)N_NODES * NCLS;        // [N, 128]
    float* h2     = h1 + (size_t)N_NODES * FDIM;          // [N, 128]
    float* logits = h2 + (size_t)N_NODES * FDIM;          // [N, 40]

    const int cls_smem  = (128 * 129 + 128 * NCLS + NCLS) * (int)sizeof(float);
    const int spmm_smem = STAGES * (8192 + 16384);   // 96 KB
    const int lin_smem  = 32768 * 2 + 65536 * 2;     // 192 KB
    cudaFuncSetAttribute(spmm_kernel, cudaFuncAttributeMaxDynamicSharedMemorySize, spmm_smem);
    cudaFuncSetAttribute(sage_linear_tc, cudaFuncAttributeMaxDynamicSharedMemorySize, lin_smem);
    cudaFuncSetAttribute(classifier_kernel, cudaFuncAttributeMaxDynamicSharedMemorySize, cls_smem);

    // 1) x -> bf16
    cvt_x_kernel<<<512, 256>>>(x);
    // 2) support = adj @ x
    spmm_kernel<<<N_NODES / BM, 256, spmm_smem>>>(adj);
    // 3) h1 = relu([x|s]@W1 + b1)  (also emits bf16 h1 into g_featb)
    sage_linear_tc<<<N_NODES / 64, 256, lin_smem>>>(x, W1, b1, h1, 1);
    // 4) support = adj @ h1
    spmm_kernel<<<N_NODES / BM, 256, spmm_smem>>>(adj);
    // 5) h2 = relu([h1|s]@W2 + b2)
    sage_linear_tc<<<N_NODES / 64, 256, lin_smem>>>(h1, W2, b2, h2, 0);
    // 6) logits + log_softmax
    classifier_kernel<<<N_NODES / 128, 128, cls_smem>>>(h2, Wl, bl, logp, logits);
}

// round 13
// speedup vs baseline: 1.2487x; 1.0116x over previous
#include <cuda_runtime.h>
#include <cuda_bf16.h>
#include <stdint.h>

#define N_NODES 16384
#define FDIM    128
#define NCLS    40

#define BM 64
#define BK 64
#define KTILES (N_NODES / BK)   // 256
#define STAGES 4

// Scratch (static device globals — no allocation allowed)
__device__ float         g_support[(size_t)N_NODES * FDIM];     // 8 MB
__device__ __nv_bfloat16 g_featb [(size_t)N_NODES * FDIM];      // 4 MB
// bf16 swizzled A tiles: [mtile 0..255][ktile 0..255][8192 B]  (512 MB)
__device__ unsigned char g_adjb[(size_t)256 * 256 * 8192];
// pre-swizzled W hi/lo tiles: [w 0..1][hi/lo][half 0..1][32768 B] (256 KB)
__device__ unsigned char g_Wprep[2 * 2 * 2 * 32768];

__device__ __forceinline__ uint32_t smaddr(const void* p) {
    return (uint32_t)__cvta_generic_to_shared(p);
}
__device__ __forceinline__ void mbar_init(uint32_t a, uint32_t cnt) {
    asm volatile("mbarrier.init.shared.b64 [%0], %1;" :: "r"(a), "r"(cnt) : "memory");
}
__device__ __forceinline__ void mbar_arrive(uint32_t a) {
    asm volatile("mbarrier.arrive.release.cta.shared.b64 _, [%0];" :: "r"(a) : "memory");
}
// Blocks while the barrier's phase == parity.
__device__ __forceinline__ void mbar_wait(uint32_t a, uint32_t parity) {
    uint32_t done;
    asm volatile(
        "{\n\t.reg .pred p;\n\t"
        "mbarrier.try_wait.parity.acquire.cta.shared::cta.b64 p, [%1], %2;\n\t"
        "selp.b32 %0, 1, 0, p;\n\t}"
        : "=r"(done) : "r"(a), "r"(parity) : "memory");
    if (!done) {
        asm volatile(
            "{\n\t.reg .pred P1;\n\t"
            "WAIT_LOOP_%=:\n\t"
            "mbarrier.try_wait.parity.acquire.cta.shared::cta.b64 P1, [%0], %1, 0x989680;\n\t"
            "@P1 bra.uni WAIT_DONE_%=;\n\t"
            "bra.uni WAIT_LOOP_%=;\n\t"
            "WAIT_DONE_%=:\n\t}"
            :: "r"(a), "r"(parity) : "memory");
    }
}

// ---------------------------------------------------------------------------
// Convert x (fp32) -> g_featb (bf16)
// ---------------------------------------------------------------------------
__global__ void cvt_x_kernel(const float* __restrict__ in) {
    int i = blockIdx.x * blockDim.x + threadIdx.x;
    int stride = gridDim.x * blockDim.x;
    const int n4 = N_NODES * FDIM / 4;
    const float4* in4 = (const float4*)in;
    __nv_bfloat162* ob = (__nv_bfloat162*)g_featb;
    for (; i < n4; i += stride) {
        float4 v = in4[i];
        ob[2 * i]     = __float22bfloat162_rn(make_float2(v.x, v.y));
        ob[2 * i + 1] = __float22bfloat162_rn(make_float2(v.z, v.w));
    }
}

// ---------------------------------------------------------------------------
// One-time W prep: W fp32 [256,128] -> bf16 hi/lo, pre-swizzled tile images.
// grid 4: block = (w, half). Layout matches linear kernel's smem exactly.
// ---------------------------------------------------------------------------
__global__ void __launch_bounds__(256)
prep_w_kernel(const float* __restrict__ W1, const float* __restrict__ W2) {
    const int w    = blockIdx.x >> 1;
    const int half = blockIdx.x & 1;
    const float* W = w ? W2 : W1;
    char* dhi = (char*)g_Wprep + w * 131072 + half * 32768;
    char* dlo = (char*)g_Wprep + w * 131072 + 65536 + half * 32768;
    const int t = threadIdx.x;
    #pragma unroll
    for (int p = 0; p < 16; ++p) {
        int idx = t + p * 256;          // 0..4095
        int r = idx >> 5, af = idx & 31;
        float4 v = *(const float4*)(W + (size_t)(half * 128 + r) * FDIM + af * 4);
        int c = af >> 1, h = af & 1;
        uint32_t off = r * 256 + (((c ^ ((r & 7) << 1)) << 4) | (h << 3));
        __nv_bfloat16 hx = __float2bfloat16(v.x), hy = __float2bfloat16(v.y);
        __nv_bfloat16 hz = __float2bfloat16(v.z), hw = __float2bfloat16(v.w);
        __nv_bfloat16 lx = __float2bfloat16(v.x - __bfloat162float(hx));
        __nv_bfloat16 ly = __float2bfloat16(v.y - __bfloat162float(hy));
        __nv_bfloat16 lz = __float2bfloat16(v.z - __bfloat162float(hz));
        __nv_bfloat16 lw = __float2bfloat16(v.w - __bfloat162float(hw));
        uint2 uh, ul;
        uh.x = ((uint32_t)*(uint16_t*)&hy << 16) | *(uint16_t*)&hx;
        uh.y = ((uint32_t)*(uint16_t*)&hw << 16) | *(uint16_t*)&hz;
        ul.x = ((uint32_t)*(uint16_t*)&ly << 16) | *(uint16_t*)&lx;
        ul.y = ((uint32_t)*(uint16_t*)&lw << 16) | *(uint16_t*)&lz;
        *(uint2*)(dhi + off) = uh;
        *(uint2*)(dlo + off) = ul;
    }
}

// ---------------------------------------------------------------------------
// SpMM: g_support[N,128] = adj_bf16 @ g_featb[N,128]
// Warp-specialized (R5 geometry): warps 0-3 consume, warps 4-7 produce.
// MODE 1: A from fp32 adj (LDG->cvt->STS) + persist bf16 tiles to g_adjb.
// MODE 2: A tiles from g_adjb via pure linear cp.async (no LDG/cvt/STS).
// CTA tile 64(M) x 128(N), BK=64, 4-stage mbarrier ring, occ 2, grid 256.
// ---------------------------------------------------------------------------
template<int MODE>
__global__ void __launch_bounds__(256, 2)
spmm_kernel(const float* __restrict__ A) {
    extern __shared__ char smem[];
    char* As = smem;                         // STAGES * 8192
    char* Bs = smem + STAGES * 8192;         // STAGES * 16384
    __shared__ uint64_t bar_full[STAGES];
    __shared__ uint64_t bar_empty[STAGES];
    const uint32_t as0 = smaddr(As);
    const uint32_t bs0 = smaddr(Bs);
    const uint32_t bf0 = smaddr(&bar_full[0]);
    const uint32_t be0 = smaddr(&bar_empty[0]);

    const int t    = threadIdx.x;
    const int lane = t & 31;
    const int warp = t >> 5;
    const int m0 = blockIdx.x * BM;

    if (t == 0) {
        #pragma unroll
        for (int s = 0; s < STAGES; ++s) {
            mbar_init(bf0 + s * 8, 128);   // producers arrive
            mbar_init(be0 + s * 8, 128);   // consumers arrive
        }
    }
    __syncthreads();

    if (warp >= 4) {
        // ===================== PRODUCER (warps 4-7) =====================
        const int pt = t - 128;            // 0..127
        char* gtile_base = (char*)g_adjb + (size_t)blockIdx.x * (256 * 8192);

        auto cpB = [&](int kt, int slot) {
            const char* gsrc = (const char*)(g_featb + (size_t)kt * BK * FDIM);
            const uint32_t sbase = bs0 + slot * 16384;
            #pragma unroll
            for (int p = 0; p < 8; ++p) {
                int idx = pt + p * 128;     // 0..1023
                int r = idx >> 4;           // 0..63
                int c = idx & 15;
                uint32_t soff = r * 256 + ((c ^ ((r & 7) << 1)) << 4);
                asm volatile("cp.async.cg.shared.global [%0], [%1], 16;\n"
                             :: "r"(sbase + soff), "l"(gsrc + (size_t)r * 256 + c * 16));
            }
        };

        if (MODE == 1) {
            const int ar = pt >> 4;            // 0..7
            const int af = pt & 15;            // float4 slot within 64-float row
            const float* Abase = A + (size_t)m0 * N_NODES;
            float4 regA[8], regB[8];

            auto ldgA = [&](int kt, float4 (&rg)[8]) {
                const float* src = Abase + (size_t)kt * BK + af * 4;
                #pragma unroll
                for (int p = 0; p < 8; ++p) {
                    int r = p * 8 + ar;
                    rg[p] = *(const float4*)(src + (size_t)r * N_NODES);
                }
            };
            auto stsA = [&](int slot, const float4 (&rg)[8], char* gts) {
                char* dst = As + slot * 8192;
                const int c = af >> 1, h = af & 1;
                #pragma unroll
                for (int p = 0; p < 8; ++p) {
                    int r = p * 8 + ar;
                    int off = r * 128 + (((c ^ (r & 7)) << 4) | (h << 3));
                    __nv_bfloat162 lo = __float22bfloat162_rn(make_float2(rg[p].x, rg[p].y));
                    __nv_bfloat162 hi = __float22bfloat162_rn(make_float2(rg[p].z, rg[p].w));
                    uint2 v;
                    v.x = *(uint32_t*)&lo;
                    v.y = *(uint32_t*)&hi;
                    *(uint2*)(dst + off) = v;
                    asm volatile("st.global.cs.v2.b32 [%0], {%1, %2};"
                                 :: "l"(gts + off), "r"(v.x), "r"(v.y) : "memory");
                }
            };

            // prologue: tile 0 into flight
            mbar_wait(be0 + 0, 1);
            cpB(0, 0);
            asm volatile("cp.async.commit_group;\n");
            ldgA(0, regA);

            #pragma unroll 1
            for (int tt = 0; tt < KTILES; tt += 2) {
                { // even tile tt (data in regA), prefetch tt+1 into regB
                    const int nt = tt + 1;
                    const int ns = nt & (STAGES - 1);
                    mbar_wait(be0 + ns * 8, ((nt >> 2) & 1) ^ 1);
                    cpB(nt, ns);
                    asm volatile("cp.async.commit_group;\n");
                    ldgA(nt, regB);
                    stsA(tt & (STAGES - 1), regA, gtile_base + (size_t)tt * 8192);
                    asm volatile("cp.async.wait_group 1;\n");
                    mbar_arrive(bf0 + (tt & (STAGES - 1)) * 8);
                }
                { // odd tile tt+1 (data in regB), prefetch tt+2 into regA
                    const int ct = tt + 1;
                    const int nt = tt + 2;
                    if (nt < KTILES) {
                        const int ns = nt & (STAGES - 1);
                        mbar_wait(be0 + ns * 8, ((nt >> 2) & 1) ^ 1);
                        cpB(nt, ns);
                        asm volatile("cp.async.commit_group;\n");
                        ldgA(nt, regA);
                        stsA(ct & (STAGES - 1), regB, gtile_base + (size_t)ct * 8192);
                        asm volatile("cp.async.wait_group 1;\n");
                    } else {
                        stsA(ct & (STAGES - 1), regB, gtile_base + (size_t)ct * 8192);
                        asm volatile("cp.async.wait_group 0;\n");
                    }
                    mbar_arrive(bf0 + (ct & (STAGES - 1)) * 8);
                }
            }
        } else {
            // MODE 2: A tiles are ready-made swizzled bf16 images in g_adjb.
            auto cpA2 = [&](int kt, int slot) {
                const char* src = gtile_base + (size_t)kt * 8192 + pt * 16;
                const uint32_t dst = as0 + slot * 8192 + pt * 16;
                #pragma unroll
                for (int p = 0; p < 4; ++p)
                    asm volatile("cp.async.cg.shared.global [%0], [%1], 16;\n"
                                 :: "r"(dst + p * 2048), "l"(src + p * 2048));
            };

            mbar_wait(be0 + 0, 1);
            cpA2(0, 0);
            cpB(0, 0);
            asm volatile("cp.async.commit_group;\n");

            #pragma unroll 1
            for (int tt = 0; tt < KTILES; ++tt) {
                const int nt = tt + 1;
                if (nt < KTILES) {
                    const int ns = nt & (STAGES - 1);
                    mbar_wait(be0 + ns * 8, ((nt >> 2) & 1) ^ 1);
                    cpA2(nt, ns);
                    cpB(nt, ns);
                    asm volatile("cp.async.commit_group;\n");
                    asm volatile("cp.async.wait_group 1;\n");
                } else {
                    asm volatile("cp.async.wait_group 0;\n");
                }
                mbar_arrive(bf0 + (tt & (STAGES - 1)) * 8);
            }
        }
    } else {
        // ===================== CONSUMER (warps 0-3) =====================
        const int wm = warp & 1;       // 0..1 (M groups of 32)
        const int wn = warp >> 1;      // 0..1 (N groups of 64)

        float acc[2][8][4];
        #pragma unroll
        for (int i = 0; i < 2; ++i)
            #pragma unroll
            for (int j = 0; j < 8; ++j)
                #pragma unroll
                for (int k = 0; k < 4; ++k) acc[i][j][k] = 0.f;

        #pragma unroll 1
        for (int tt = 0; tt < KTILES; ++tt) {
            const int slot = tt & (STAGES - 1);
            mbar_wait(bf0 + slot * 8, (tt >> 2) & 1);
            const uint32_t ab = as0 + slot * 8192;
            const uint32_t bb = bs0 + slot * 16384;
            #pragma unroll
            for (int ks = 0; ks < 4; ++ks) {
                uint32_t a[2][4];
                #pragma unroll
                for (int mt = 0; mt < 2; ++mt) {
                    int r = wm * 32 + mt * 16 + (lane & 15);
                    int c = ks * 2 + (lane >> 4);
                    uint32_t addr = ab + r * 128 + ((c ^ (r & 7)) << 4);
                    asm volatile("ldmatrix.sync.aligned.m8n8.x4.shared.b16 {%0,%1,%2,%3}, [%4];\n"
                        : "=r"(a[mt][0]), "=r"(a[mt][1]), "=r"(a[mt][2]), "=r"(a[mt][3])
                        : "r"(addr));
                }
                uint32_t b[8][2];
                #pragma unroll
                for (int nt = 0; nt < 8; ++nt) {
                    int r = ks * 16 + (lane & 15);
                    int c = wn * 8 + nt;
                    uint32_t addr = bb + r * 256 + ((c ^ ((r & 7) << 1)) << 4);
                    asm volatile("ldmatrix.sync.aligned.m8n8.x2.trans.shared.b16 {%0,%1}, [%2];\n"
                        : "=r"(b[nt][0]), "=r"(b[nt][1]) : "r"(addr));
                }
                #pragma unroll
                for (int mt = 0; mt < 2; ++mt)
                    #pragma unroll
                    for (int nt = 0; nt < 8; ++nt) {
                        asm volatile(
                            "mma.sync.aligned.m16n8k16.row.col.f32.bf16.bf16.f32 "
                            "{%0,%1,%2,%3}, {%4,%5,%6,%7}, {%8,%9}, {%0,%1,%2,%3};\n"
                            : "+f"(acc[mt][nt][0]), "+f"(acc[mt][nt][1]),
                              "+f"(acc[mt][nt][2]), "+f"(acc[mt][nt][3])
                            : "r"(a[mt][0]), "r"(a[mt][1]), "r"(a[mt][2]), "r"(a[mt][3]),
                              "r"(b[nt][0]), "r"(b[nt][1]));
                    }
            }
            mbar_arrive(be0 + slot * 8);
        }

        // Epilogue: fragment -> g_support (fp32, row-major)
        float* Cp = g_support + (size_t)m0 * FDIM;
        #pragma unroll
        for (int mt = 0; mt < 2; ++mt) {
            int r0 = wm * 32 + mt * 16 + (lane >> 2);
            #pragma unroll
            for (int nt = 0; nt < 8; ++nt) {
                int c0 = wn * 64 + nt * 8 + (lane & 3) * 2;
                *(float2*)(Cp + (size_t)r0 * FDIM + c0)       = make_float2(acc[mt][nt][0], acc[mt][nt][1]);
                *(float2*)(Cp + (size_t)(r0 + 8) * FDIM + c0) = make_float2(acc[mt][nt][2], acc[mt][nt][3]);
            }
        }
    }
}

// ---------------------------------------------------------------------------
// Tensor-core SAGE linear, bf16 hi/lo split (fp32-accurate):
//   h = relu([X | g_support] @ W + b)
// A halves converted in-kernel (fp32 -> hi/lo); W tiles cp.async'd from the
// pre-swizzled g_Wprep images. CTA 64 rows x 128 cols, 256 threads,
// warp grid 2(M) x 4(N), K=256. smem 192KB, occ 1, grid 256.
// ---------------------------------------------------------------------------
__global__ void __launch_bounds__(256)
sage_linear_tc(const float* __restrict__ X,
               int wsel,
               const float* __restrict__ bias,
               float* __restrict__ out,
               int write_bf16) {
    extern __shared__ char sm[];
    char* Ahi = sm;               // 2 * 16KB
    char* Alo = sm + 32768;       // 2 * 16KB
    char* Whi = sm + 65536;       // 2 * 32KB
    char* Wlo = sm + 131072;      // 2 * 32KB
    const uint32_t ahi0 = smaddr(Ahi);
    const uint32_t alo0 = smaddr(Alo);
    const uint32_t whi0 = smaddr(Whi);
    const uint32_t wlo0 = smaddr(Wlo);

    const int t = threadIdx.x;
    const int lane = t & 31;
    const int warp = t >> 5;
    const int wm = warp & 1;       // 2 M groups of 32 rows
    const int wn = warp >> 1;      // 4 N groups of 32 cols
    const int m0 = blockIdx.x * 64;

    // W hi/lo tiles: pure cp.async from pre-swizzled global (64KB each)
    {
        const char* src_hi = (const char*)g_Wprep + wsel * 131072;
        const char* src_lo = src_hi + 65536;
        #pragma unroll
        for (int p = 0; p < 16; ++p) {
            int idx = t + p * 256;              // 0..4095 16B chunks
            asm volatile("cp.async.cg.shared.global [%0], [%1], 16;\n"
                :: "r"(whi0 + idx * 16), "l"(src_hi + idx * 16));
            asm volatile("cp.async.cg.shared.global [%0], [%1], 16;\n"
                :: "r"(wlo0 + idx * 16), "l"(src_lo + idx * 16));
        }
        asm volatile("cp.async.commit_group;\n");
    }

    // Stage A halves (fp32 -> bf16 hi/lo, swizzled)
    #pragma unroll
    for (int half = 0; half < 2; ++half) {
        const float* src = half ? (g_support + (size_t)m0 * FDIM)
                                : (X + (size_t)m0 * FDIM);
        char* dhi = Ahi + half * 16384;
        char* dlo = Alo + half * 16384;
        #pragma unroll
        for (int p = 0; p < 8; ++p) {
            int idx = t + p * 256;          // 0..2047
            int r = idx >> 5, af = idx & 31;
            float4 v = *(const float4*)(src + (size_t)r * FDIM + af * 4);
            int c = af >> 1, h = af & 1;
            uint32_t off = r * 256 + (((c ^ ((r & 7) << 1)) << 4) | (h << 3));
            __nv_bfloat16 hx = __float2bfloat16(v.x), hy = __float2bfloat16(v.y);
            __nv_bfloat16 hz = __float2bfloat16(v.z), hw = __float2bfloat16(v.w);
            __nv_bfloat16 lx = __float2bfloat16(v.x - __bfloat162float(hx));
            __nv_bfloat16 ly = __float2bfloat16(v.y - __bfloat162float(hy));
            __nv_bfloat16 lz = __float2bfloat16(v.z - __bfloat162float(hz));
            __nv_bfloat16 lw = __float2bfloat16(v.w - __bfloat162float(hw));
            uint2 uh, ul;
            uh.x = ((uint32_t)*(uint16_t*)&hy << 16) | *(uint16_t*)&hx;
            uh.y = ((uint32_t)*(uint16_t*)&hw << 16) | *(uint16_t*)&hz;
            ul.x = ((uint32_t)*(uint16_t*)&ly << 16) | *(uint16_t*)&lx;
            ul.y = ((uint32_t)*(uint16_t*)&lw << 16) | *(uint16_t*)&lz;
            *(uint2*)(dhi + off) = uh;
            *(uint2*)(dlo + off) = ul;
        }
    }
    asm volatile("cp.async.wait_group 0;\n");
    __syncthreads();

    float acc[2][4][4];
    #pragma unroll
    for (int i = 0; i < 2; ++i)
        #pragma unroll
        for (int j = 0; j < 4; ++j)
            #pragma unroll
            for (int k = 0; k < 4; ++k) acc[i][j][k] = 0.f;

    #pragma unroll
    for (int half = 0; half < 2; ++half) {
        const uint32_t abh = ahi0 + half * 16384;
        const uint32_t abl = alo0 + half * 16384;
        const uint32_t wbh = whi0 + half * 32768;
        const uint32_t wbl = wlo0 + half * 32768;
        #pragma unroll
        for (int ks = 0; ks < 8; ++ks) {
            uint32_t ah[2][4], al[2][4];
            #pragma unroll
            for (int mt = 0; mt < 2; ++mt) {
                int r = wm * 32 + mt * 16 + (lane & 15);
                int c = ks * 2 + (lane >> 4);
                uint32_t sw = r * 256 + ((c ^ ((r & 7) << 1)) << 4);
                asm volatile("ldmatrix.sync.aligned.m8n8.x4.shared.b16 {%0,%1,%2,%3}, [%4];\n"
                    : "=r"(ah[mt][0]), "=r"(ah[mt][1]), "=r"(ah[mt][2]), "=r"(ah[mt][3])
                    : "r"(abh + sw));
                asm volatile("ldmatrix.sync.aligned.m8n8.x4.shared.b16 {%0,%1,%2,%3}, [%4];\n"
                    : "=r"(al[mt][0]), "=r"(al[mt][1]), "=r"(al[mt][2]), "=r"(al[mt][3])
                    : "r"(abl + sw));
            }
            #pragma unroll
            for (int nt = 0; nt < 4; ++nt) {
                int r = ks * 16 + (lane & 15);
                int c = wn * 4 + nt;
                uint32_t sw = r * 256 + ((c ^ ((r & 7) << 1)) << 4);
                uint32_t bh0, bh1, bl0, bl1;
                asm volatile("ldmatrix.sync.aligned.m8n8.x2.trans.shared.b16 {%0,%1}, [%2];\n"
                    : "=r"(bh0), "=r"(bh1) : "r"(wbh + sw));
                asm volatile("ldmatrix.sync.aligned.m8n8.x2.trans.shared.b16 {%0,%1}, [%2];\n"
                    : "=r"(bl0), "=r"(bl1) : "r"(wbl + sw));
                #pragma unroll
                for (int mt = 0; mt < 2; ++mt) {
                    asm volatile(
                        "mma.sync.aligned.m16n8k16.row.col.f32.bf16.bf16.f32 "
                        "{%0,%1,%2,%3}, {%4,%5,%6,%7}, {%8,%9}, {%0,%1,%2,%3};\n"
                        : "+f"(acc[mt][nt][0]), "+f"(acc[mt][nt][1]),
                          "+f"(acc[mt][nt][2]), "+f"(acc[mt][nt][3])
                        : "r"(ah[mt][0]), "r"(ah[mt][1]), "r"(ah[mt][2]), "r"(ah[mt][3]),
                          "r"(bh0), "r"(bh1));
                    asm volatile(
                        "mma.sync.aligned.m16n8k16.row.col.f32.bf16.bf16.f32 "
                        "{%0,%1,%2,%3}, {%4,%5,%6,%7}, {%8,%9}, {%0,%1,%2,%3};\n"
                        : "+f"(acc[mt][nt][0]), "+f"(acc[mt][nt][1]),
                          "+f"(acc[mt][nt][2]), "+f"(acc[mt][nt][3])
                        : "r"(al[mt][0]), "r"(al[mt][1]), "r"(al[mt][2]), "r"(al[mt][3]),
                          "r"(bh0), "r"(bh1));
                    asm volatile(
                        "mma.sync.aligned.m16n8k16.row.col.f32.bf16.bf16.f32 "
                        "{%0,%1,%2,%3}, {%4,%5,%6,%7}, {%8,%9}, {%0,%1,%2,%3};\n"
                        : "+f"(acc[mt][nt][0]), "+f"(acc[mt][nt][1]),
                          "+f"(acc[mt][nt][2]), "+f"(acc[mt][nt][3])
                        : "r"(ah[mt][0]), "r"(ah[mt][1]), "r"(ah[mt][2]), "r"(ah[mt][3]),
                          "r"(bl0), "r"(bl1));
                }
            }
        }
    }

    // Epilogue: bias + relu -> fp32 out (+ optional bf16 g_featb)
    #pragma unroll
    for (int mt = 0; mt < 2; ++mt) {
        int r0 = m0 + wm * 32 + mt * 16 + (lane >> 2);
        #pragma unroll
        for (int nt = 0; nt < 4; ++nt) {
            int c0 = wn * 32 + nt * 8 + (lane & 3) * 2;
            float bv0 = __ldg(&bias[c0]);
            float bv1 = __ldg(&bias[c0 + 1]);
            float o00 = fmaxf(acc[mt][nt][0] + bv0, 0.f);
            float o01 = fmaxf(acc[mt][nt][1] + bv1, 0.f);
            float o10 = fmaxf(acc[mt][nt][2] + bv0, 0.f);
            float o11 = fmaxf(acc[mt][nt][3] + bv1, 0.f);
            *(float2*)(out + (size_t)r0 * FDIM + c0)       = make_float2(o00, o01);
            *(float2*)(out + (size_t)(r0 + 8) * FDIM + c0) = make_float2(o10, o11);
            if (write_bf16) {
                __nv_bfloat162 p0 = __float22bfloat162_rn(make_float2(o00, o01));
                __nv_bfloat162 p1 = __float22bfloat162_rn(make_float2(o10, o11));
                *(__nv_bfloat162*)(g_featb + (size_t)r0 * FDIM + c0)       = p0;
                *(__nv_bfloat162*)(g_featb + (size_t)(r0 + 8) * FDIM + c0) = p1;
            }
        }
    }
}

// ---------------------------------------------------------------------------
// logits = h2 @ Wl + bl ; log_probs = logits - logsumexp(logits)
// ---------------------------------------------------------------------------
__global__ void __launch_bounds__(128)
classifier_kernel(const float* __restrict__ H,
                  const float* __restrict__ Wl,
                  const float* __restrict__ bl,
                  float* __restrict__ logp,
                  float* __restrict__ logits) {
    extern __shared__ float sh[];
    float* Hs  = sh;                  // 128*129
    float* Wls = sh + 128 * 129;      // 128*40
    float* bls = Wls + 128 * NCLS;    // 40
    const int t = threadIdx.x;
    const int row0 = blockIdx.x * 128;

    for (int j = 0; j < 128; ++j)
        Hs[j * 129 + t] = H[(size_t)(row0 + j) * FDIM + t];
    for (int idx = t; idx < 128 * NCLS; idx += 128)
        Wls[idx] = Wl[idx];
    if (t < NCLS) bls[t] = bl[t];
    __syncthreads();

    float acc[NCLS];
    #pragma unroll
    for (int c = 0; c < NCLS; ++c) acc[c] = bls[c];

    const float* hr = &Hs[t * 129];
    #pragma unroll 4
    for (int k = 0; k < FDIM; ++k) {
        float xv = hr[k];
        #pragma unroll
        for (int c = 0; c < NCLS; c += 4) {
            float4 w = *(const float4*)&Wls[k * NCLS + c];
            acc[c + 0] = fmaf(xv, w.x, acc[c + 0]);
            acc[c + 1] = fmaf(xv, w.y, acc[c + 1]);
            acc[c + 2] = fmaf(xv, w.z, acc[c + 2]);
            acc[c + 3] = fmaf(xv, w.w, acc[c + 3]);
        }
    }

    float m = acc[0];
    #pragma unroll
    for (int c = 1; c < NCLS; ++c) m = fmaxf(m, acc[c]);
    float s = 0.f;
    #pragma unroll
    for (int c = 0; c < NCLS; ++c) s += __expf(acc[c] - m);
    float lse = m + __logf(s);

    size_t ro = (size_t)(row0 + t) * NCLS;
    #pragma unroll
    for (int c = 0; c < NCLS; ++c) {
        logits[ro + c] = acc[c];
        logp[ro + c]   = acc[c] - lse;
    }
}

// ---------------------------------------------------------------------------
extern "C" void kernel_launch(void* const* d_in, const int* in_sizes, int n_in,
                              void* d_out, int out_size) {
    (void)in_sizes; (void)n_in; (void)out_size;
    const float* x   = (const float*)d_in[0];
    const float* adj = (const float*)d_in[1];
    const float* W1  = (const float*)d_in[2];
    const float* b1  = (const float*)d_in[3];
    const float* W2  = (const float*)d_in[4];
    const float* b2  = (const float*)d_in[5];
    const float* Wl  = (const float*)d_in[6];
    const float* bl  = (const float*)d_in[7];

    float* out    = (float*)d_out;
    float* logp   = out;                                  // [N, 40]
    float* h1     = logp + (size_t)N_NODES * NCLS;        // [N, 128]
    float* h2     = h1 + (size_t)N_NODES * FDIM;          // [N, 128]
    float* logits = h2 + (size_t)N_NODES * FDIM;          // [N, 40]

    const int cls_smem  = (128 * 129 + 128 * NCLS + NCLS) * (int)sizeof(float);
    const int spmm_smem = STAGES * (8192 + 16384);   // 96 KB
    const int lin_smem  = 32768 * 2 + 65536 * 2;     // 192 KB
    cudaFuncSetAttribute(spmm_kernel<1>, cudaFuncAttributeMaxDynamicSharedMemorySize, spmm_smem);
    cudaFuncSetAttribute(spmm_kernel<2>, cudaFuncAttributeMaxDynamicSharedMemorySize, spmm_smem);
    cudaFuncSetAttribute(sage_linear_tc, cudaFuncAttributeMaxDynamicSharedMemorySize, lin_smem);
    cudaFuncSetAttribute(classifier_kernel, cudaFuncAttributeMaxDynamicSharedMemorySize, cls_smem);

    // 0) W1/W2 -> pre-swizzled bf16 hi/lo tiles
    prep_w_kernel<<<4, 256>>>(W1, W2);
    // 1) x -> bf16
    cvt_x_kernel<<<512, 256>>>(x);
    // 2) support = adj @ x  (also persists bf16 swizzled adj tiles)
    spmm_kernel<1><<<N_NODES / BM, 256, spmm_smem>>>(adj);
    // 3) h1 = relu([x|s]@W1 + b1)  (also emits bf16 h1 into g_featb)
    sage_linear_tc<<<N_NODES / 64, 256, lin_smem>>>(x, 0, b1, h1, 1);
    // 4) support = adj @ h1  (A from bf16 tile cache)
    spmm_kernel<2><<<N_NODES / BM, 256, spmm_smem>>>(adj);
    // 5) h2 = relu([h1|s]@W2 + b2)
    sage_linear_tc<<<N_NODES / 64, 256, lin_smem>>>(h1, 1, b2, h2, 0);
    // 6) logits + log_softmax
    classifier_kernel<<<N_NODES / 128, 128, cls_smem>>>(h2, Wl, bl, logp, logits);
}

// round 14
// speedup vs baseline: 1.2594x; 1.0086x over previous
#include <cuda_runtime.h>
#include <cuda_bf16.h>
#include <stdint.h>

#define N_NODES 16384
#define FDIM    128
#define NCLS    40

#define BM 64
#define BK 64
#define KTILES (N_NODES / BK)   // 256
#define STAGES 4

// Scratch (static device globals — no allocation allowed)
__device__ float         g_support[(size_t)N_NODES * FDIM];     // 8 MB
__device__ __nv_bfloat16 g_featb [(size_t)N_NODES * FDIM];      // 4 MB
// bf16 swizzled A tiles: [mtile 0..255][ktile 0..255][8192 B]  (512 MB)
__device__ unsigned char g_adjb[(size_t)256 * 256 * 8192];
// pre-swizzled W hi/lo tiles: [w 0..1][hi/lo][half 0..1][32768 B] (256 KB)
__device__ unsigned char g_Wprep[2 * 2 * 2 * 32768];

__device__ __forceinline__ uint32_t smaddr(const void* p) {
    return (uint32_t)__cvta_generic_to_shared(p);
}
__device__ __forceinline__ void mbar_init(uint32_t a, uint32_t cnt) {
    asm volatile("mbarrier.init.shared.b64 [%0], %1;" :: "r"(a), "r"(cnt) : "memory");
}
__device__ __forceinline__ void mbar_arrive(uint32_t a) {
    asm volatile("mbarrier.arrive.release.cta.shared.b64 _, [%0];" :: "r"(a) : "memory");
}
// Blocks while the barrier's phase == parity.
__device__ __forceinline__ void mbar_wait(uint32_t a, uint32_t parity) {
    uint32_t done;
    asm volatile(
        "{\n\t.reg .pred p;\n\t"
        "mbarrier.try_wait.parity.acquire.cta.shared::cta.b64 p, [%1], %2;\n\t"
        "selp.b32 %0, 1, 0, p;\n\t}"
        : "=r"(done) : "r"(a), "r"(parity) : "memory");
    if (!done) {
        asm volatile(
            "{\n\t.reg .pred P1;\n\t"
            "WAIT_LOOP_%=:\n\t"
            "mbarrier.try_wait.parity.acquire.cta.shared::cta.b64 P1, [%0], %1, 0x989680;\n\t"
            "@P1 bra.uni WAIT_DONE_%=;\n\t"
            "bra.uni WAIT_LOOP_%=;\n\t"
            "WAIT_DONE_%=:\n\t}"
            :: "r"(a), "r"(parity) : "memory");
    }
}

// ---------------------------------------------------------------------------
// Convert x (fp32) -> g_featb (bf16)
// ---------------------------------------------------------------------------
__global__ void cvt_x_kernel(const float* __restrict__ in) {
    int i = blockIdx.x * blockDim.x + threadIdx.x;
    int stride = gridDim.x * blockDim.x;
    const int n4 = N_NODES * FDIM / 4;
    const float4* in4 = (const float4*)in;
    __nv_bfloat162* ob = (__nv_bfloat162*)g_featb;
    for (; i < n4; i += stride) {
        float4 v = in4[i];
        ob[2 * i]     = __float22bfloat162_rn(make_float2(v.x, v.y));
        ob[2 * i + 1] = __float22bfloat162_rn(make_float2(v.z, v.w));
    }
}

// ---------------------------------------------------------------------------
// One-time W prep: W fp32 [256,128] -> bf16 hi/lo, pre-swizzled tile images.
// grid 4: block = (w, half). Layout matches linear kernel's smem exactly.
// ---------------------------------------------------------------------------
__global__ void __launch_bounds__(256)
prep_w_kernel(const float* __restrict__ W1, const float* __restrict__ W2) {
    const int w    = blockIdx.x >> 1;
    const int half = blockIdx.x & 1;
    const float* W = w ? W2 : W1;
    char* dhi = (char*)g_Wprep + w * 131072 + half * 32768;
    char* dlo = (char*)g_Wprep + w * 131072 + 65536 + half * 32768;
    const int t = threadIdx.x;
    #pragma unroll
    for (int p = 0; p < 16; ++p) {
        int idx = t + p * 256;          // 0..4095
        int r = idx >> 5, af = idx & 31;
        float4 v = *(const float4*)(W + (size_t)(half * 128 + r) * FDIM + af * 4);
        int c = af >> 1, h = af & 1;
        uint32_t off = r * 256 + (((c ^ ((r & 7) << 1)) << 4) | (h << 3));
        __nv_bfloat16 hx = __float2bfloat16(v.x), hy = __float2bfloat16(v.y);
        __nv_bfloat16 hz = __float2bfloat16(v.z), hw = __float2bfloat16(v.w);
        __nv_bfloat16 lx = __float2bfloat16(v.x - __bfloat162float(hx));
        __nv_bfloat16 ly = __float2bfloat16(v.y - __bfloat162float(hy));
        __nv_bfloat16 lz = __float2bfloat16(v.z - __bfloat162float(hz));
        __nv_bfloat16 lw = __float2bfloat16(v.w - __bfloat162float(hw));
        uint2 uh, ul;
        uh.x = ((uint32_t)*(uint16_t*)&hy << 16) | *(uint16_t*)&hx;
        uh.y = ((uint32_t)*(uint16_t*)&hw << 16) | *(uint16_t*)&hz;
        ul.x = ((uint32_t)*(uint16_t*)&ly << 16) | *(uint16_t*)&lx;
        ul.y = ((uint32_t)*(uint16_t*)&lw << 16) | *(uint16_t*)&lz;
        *(uint2*)(dhi + off) = uh;
        *(uint2*)(dlo + off) = ul;
    }
}

// ---------------------------------------------------------------------------
// SpMM: g_support[N,128] = adj_bf16 @ g_featb[N,128]
// Warp-specialized (R5 geometry): warps 0-3 consume, warps 4-7 produce.
// MODE 1: A from fp32 adj (LDG->cvt->STS) + persist bf16 tiles to g_adjb.
// MODE 2: A tiles from g_adjb via pure linear cp.async (no LDG/cvt/STS).
// CTA tile 64(M) x 128(N), BK=64, 4-stage mbarrier ring, occ 2, grid 256.
// ---------------------------------------------------------------------------
template<int MODE>
__global__ void __launch_bounds__(256, 2)
spmm_kernel(const float* __restrict__ A) {
    extern __shared__ char smem[];
    char* As = smem;                         // STAGES * 8192
    char* Bs = smem + STAGES * 8192;         // STAGES * 16384
    __shared__ uint64_t bar_full[STAGES];
    __shared__ uint64_t bar_empty[STAGES];
    const uint32_t as0 = smaddr(As);
    const uint32_t bs0 = smaddr(Bs);
    const uint32_t bf0 = smaddr(&bar_full[0]);
    const uint32_t be0 = smaddr(&bar_empty[0]);

    const int t    = threadIdx.x;
    const int lane = t & 31;
    const int warp = t >> 5;
    const int m0 = blockIdx.x * BM;

    if (t == 0) {
        #pragma unroll
        for (int s = 0; s < STAGES; ++s) {
            mbar_init(bf0 + s * 8, 128);   // producers arrive
            mbar_init(be0 + s * 8, 128);   // consumers arrive
        }
    }
    __syncthreads();

    if (warp >= 4) {
        // ===================== PRODUCER (warps 4-7) =====================
        const int pt = t - 128;            // 0..127
        char* gtile_base = (char*)g_adjb + (size_t)blockIdx.x * (256 * 8192);

        auto cpB = [&](int kt, int slot) {
            const char* gsrc = (const char*)(g_featb + (size_t)kt * BK * FDIM);
            const uint32_t sbase = bs0 + slot * 16384;
            #pragma unroll
            for (int p = 0; p < 8; ++p) {
                int idx = pt + p * 128;     // 0..1023
                int r = idx >> 4;           // 0..63
                int c = idx & 15;
                uint32_t soff = r * 256 + ((c ^ ((r & 7) << 1)) << 4);
                asm volatile("cp.async.cg.shared.global [%0], [%1], 16;\n"
                             :: "r"(sbase + soff), "l"(gsrc + (size_t)r * 256 + c * 16));
            }
        };

        if (MODE == 1) {
            const int ar = pt >> 4;            // 0..7
            const int af = pt & 15;            // float4 slot within 64-float row
            const float* Abase = A + (size_t)m0 * N_NODES;
            float4 regA[8], regB[8];

            auto ldgA = [&](int kt, float4 (&rg)[8]) {
                const float* src = Abase + (size_t)kt * BK + af * 4;
                #pragma unroll
                for (int p = 0; p < 8; ++p) {
                    int r = p * 8 + ar;
                    rg[p] = *(const float4*)(src + (size_t)r * N_NODES);
                }
            };
            auto stsA = [&](int slot, const float4 (&rg)[8], char* gts) {
                char* dst = As + slot * 8192;
                const int c = af >> 1, h = af & 1;
                #pragma unroll
                for (int p = 0; p < 8; ++p) {
                    int r = p * 8 + ar;
                    int off = r * 128 + (((c ^ (r & 7)) << 4) | (h << 3));
                    __nv_bfloat162 lo = __float22bfloat162_rn(make_float2(rg[p].x, rg[p].y));
                    __nv_bfloat162 hi = __float22bfloat162_rn(make_float2(rg[p].z, rg[p].w));
                    uint2 v;
                    v.x = *(uint32_t*)&lo;
                    v.y = *(uint32_t*)&hi;
                    *(uint2*)(dst + off) = v;
                    asm volatile("st.global.cs.v2.b32 [%0], {%1, %2};"
                                 :: "l"(gts + off), "r"(v.x), "r"(v.y) : "memory");
                }
            };

            // prologue: tile 0 into flight
            mbar_wait(be0 + 0, 1);
            cpB(0, 0);
            asm volatile("cp.async.commit_group;\n");
            ldgA(0, regA);

            #pragma unroll 1
            for (int tt = 0; tt < KTILES; tt += 2) {
                { // even tile tt (data in regA), prefetch tt+1 into regB
                    const int nt = tt + 1;
                    const int ns = nt & (STAGES - 1);
                    mbar_wait(be0 + ns * 8, ((nt >> 2) & 1) ^ 1);
                    cpB(nt, ns);
                    asm volatile("cp.async.commit_group;\n");
                    ldgA(nt, regB);
                    stsA(tt & (STAGES - 1), regA, gtile_base + (size_t)tt * 8192);
                    asm volatile("cp.async.wait_group 1;\n");
                    mbar_arrive(bf0 + (tt & (STAGES - 1)) * 8);
                }
                { // odd tile tt+1 (data in regB), prefetch tt+2 into regA
                    const int ct = tt + 1;
                    const int nt = tt + 2;
                    if (nt < KTILES) {
                        const int ns = nt & (STAGES - 1);
                        mbar_wait(be0 + ns * 8, ((nt >> 2) & 1) ^ 1);
                        cpB(nt, ns);
                        asm volatile("cp.async.commit_group;\n");
                        ldgA(nt, regA);
                        stsA(ct & (STAGES - 1), regB, gtile_base + (size_t)ct * 8192);
                        asm volatile("cp.async.wait_group 1;\n");
                    } else {
                        stsA(ct & (STAGES - 1), regB, gtile_base + (size_t)ct * 8192);
                        asm volatile("cp.async.wait_group 0;\n");
                    }
                    mbar_arrive(bf0 + (ct & (STAGES - 1)) * 8);
                }
            }
        } else {
            // MODE 2: A tiles are ready-made swizzled bf16 images in g_adjb.
            auto cpA2 = [&](int kt, int slot) {
                const char* src = gtile_base + (size_t)kt * 8192 + pt * 16;
                const uint32_t dst = as0 + slot * 8192 + pt * 16;
                #pragma unroll
                for (int p = 0; p < 4; ++p)
                    asm volatile("cp.async.cg.shared.global [%0], [%1], 16;\n"
                                 :: "r"(dst + p * 2048), "l"(src + p * 2048));
            };

            mbar_wait(be0 + 0, 1);
            cpA2(0, 0);
            cpB(0, 0);
            asm volatile("cp.async.commit_group;\n");

            #pragma unroll 1
            for (int tt = 0; tt < KTILES; ++tt) {
                const int nt = tt + 1;
                if (nt < KTILES) {
                    const int ns = nt & (STAGES - 1);
                    mbar_wait(be0 + ns * 8, ((nt >> 2) & 1) ^ 1);
                    cpA2(nt, ns);
                    cpB(nt, ns);
                    asm volatile("cp.async.commit_group;\n");
                    asm volatile("cp.async.wait_group 1;\n");
                } else {
                    asm volatile("cp.async.wait_group 0;\n");
                }
                mbar_arrive(bf0 + (tt & (STAGES - 1)) * 8);
            }
        }
    } else {
        // ===================== CONSUMER (warps 0-3) =====================
        const int wm = warp & 1;       // 0..1 (M groups of 32)
        const int wn = warp >> 1;      // 0..1 (N groups of 64)

        float acc[2][8][4];
        #pragma unroll
        for (int i = 0; i < 2; ++i)
            #pragma unroll
            for (int j = 0; j < 8; ++j)
                #pragma unroll
                for (int k = 0; k < 4; ++k) acc[i][j][k] = 0.f;

        #pragma unroll 1
        for (int tt = 0; tt < KTILES; ++tt) {
            const int slot = tt & (STAGES - 1);
            mbar_wait(bf0 + slot * 8, (tt >> 2) & 1);
            const uint32_t ab = as0 + slot * 8192;
            const uint32_t bb = bs0 + slot * 16384;
            #pragma unroll
            for (int ks = 0; ks < 4; ++ks) {
                uint32_t a[2][4];
                #pragma unroll
                for (int mt = 0; mt < 2; ++mt) {
                    int r = wm * 32 + mt * 16 + (lane & 15);
                    int c = ks * 2 + (lane >> 4);
                    uint32_t addr = ab + r * 128 + ((c ^ (r & 7)) << 4);
                    asm volatile("ldmatrix.sync.aligned.m8n8.x4.shared.b16 {%0,%1,%2,%3}, [%4];\n"
                        : "=r"(a[mt][0]), "=r"(a[mt][1]), "=r"(a[mt][2]), "=r"(a[mt][3])
                        : "r"(addr));
                }
                uint32_t b[8][2];
                #pragma unroll
                for (int nt = 0; nt < 8; ++nt) {
                    int r = ks * 16 + (lane & 15);
                    int c = wn * 8 + nt;
                    uint32_t addr = bb + r * 256 + ((c ^ ((r & 7) << 1)) << 4);
                    asm volatile("ldmatrix.sync.aligned.m8n8.x2.trans.shared.b16 {%0,%1}, [%2];\n"
                        : "=r"(b[nt][0]), "=r"(b[nt][1]) : "r"(addr));
                }
                #pragma unroll
                for (int mt = 0; mt < 2; ++mt)
                    #pragma unroll
                    for (int nt = 0; nt < 8; ++nt) {
                        asm volatile(
                            "mma.sync.aligned.m16n8k16.row.col.f32.bf16.bf16.f32 "
                            "{%0,%1,%2,%3}, {%4,%5,%6,%7}, {%8,%9}, {%0,%1,%2,%3};\n"
                            : "+f"(acc[mt][nt][0]), "+f"(acc[mt][nt][1]),
                              "+f"(acc[mt][nt][2]), "+f"(acc[mt][nt][3])
                            : "r"(a[mt][0]), "r"(a[mt][1]), "r"(a[mt][2]), "r"(a[mt][3]),
                              "r"(b[nt][0]), "r"(b[nt][1]));
                    }
            }
            mbar_arrive(be0 + slot * 8);
        }

        // Epilogue: fragment -> g_support (fp32, row-major)
        float* Cp = g_support + (size_t)m0 * FDIM;
        #pragma unroll
        for (int mt = 0; mt < 2; ++mt) {
            int r0 = wm * 32 + mt * 16 + (lane >> 2);
            #pragma unroll
            for (int nt = 0; nt < 8; ++nt) {
                int c0 = wn * 64 + nt * 8 + (lane & 3) * 2;
                *(float2*)(Cp + (size_t)r0 * FDIM + c0)       = make_float2(acc[mt][nt][0], acc[mt][nt][1]);
                *(float2*)(Cp + (size_t)(r0 + 8) * FDIM + c0) = make_float2(acc[mt][nt][2], acc[mt][nt][3]);
            }
        }
    }
}

// ---------------------------------------------------------------------------
// Tensor-core SAGE linear, bf16 hi/lo split (fp32-accurate), SPLIT-K for occ 2:
//   h = relu([X | g_support] @ W + b)
// K=256 processed as two sequential halves reusing ONE 96KB smem footprint
// (A hi/lo 32KB + W hi/lo 64KB) -> occ 2, staging of one CTA overlaps compute
// of the other. W tiles cp.async'd from pre-swizzled g_Wprep images.
// CTA 64 rows x 128 cols, 256 threads, warp grid 2(M) x 4(N).
// ---------------------------------------------------------------------------
__global__ void __launch_bounds__(256, 2)
sage_linear_tc(const float* __restrict__ X,
               int wsel,
               const float* __restrict__ bias,
               float* __restrict__ out,
               int write_bf16) {
    extern __shared__ char sm[];
    char* Ahi = sm;               // 16KB (64 x 128 bf16, swizzled 256B rows)
    char* Alo = sm + 16384;       // 16KB
    char* Whi = sm + 32768;       // 32KB (128 x 128 bf16)
    char* Wlo = sm + 65536;       // 32KB
    const uint32_t ahi0 = smaddr(Ahi);
    const uint32_t alo0 = smaddr(Alo);
    const uint32_t whi0 = smaddr(Whi);
    const uint32_t wlo0 = smaddr(Wlo);

    const int t = threadIdx.x;
    const int lane = t & 31;
    const int warp = t >> 5;
    const int wm = warp & 1;       // 2 M groups of 32 rows
    const int wn = warp >> 1;      // 4 N groups of 32 cols
    const int m0 = blockIdx.x * 64;

    float acc[2][4][4];
    #pragma unroll
    for (int i = 0; i < 2; ++i)
        #pragma unroll
        for (int j = 0; j < 4; ++j)
            #pragma unroll
            for (int k = 0; k < 4; ++k) acc[i][j][k] = 0.f;

    #pragma unroll 1
    for (int half = 0; half < 2; ++half) {
        // W hi/lo for this K-half: pure cp.async from pre-swizzled global
        {
            const char* src_hi = (const char*)g_Wprep + wsel * 131072 + half * 32768;
            const char* src_lo = src_hi + 65536;
            #pragma unroll
            for (int p = 0; p < 8; ++p) {
                int idx = t + p * 256;              // 0..2047 16B chunks
                asm volatile("cp.async.cg.shared.global [%0], [%1], 16;\n"
                    :: "r"(whi0 + idx * 16), "l"(src_hi + idx * 16));
                asm volatile("cp.async.cg.shared.global [%0], [%1], 16;\n"
                    :: "r"(wlo0 + idx * 16), "l"(src_lo + idx * 16));
            }
            asm volatile("cp.async.commit_group;\n");
        }

        // Stage A for this K-half (fp32 -> bf16 hi/lo, swizzled)
        {
            const float* src = half ? (g_support + (size_t)m0 * FDIM)
                                    : (X + (size_t)m0 * FDIM);
            #pragma unroll
            for (int p = 0; p < 8; ++p) {
                int idx = t + p * 256;          // 0..2047
                int r = idx >> 5, af = idx & 31;
                float4 v = *(const float4*)(src + (size_t)r * FDIM + af * 4);
                int c = af >> 1, h = af & 1;
                uint32_t off = r * 256 + (((c ^ ((r & 7) << 1)) << 4) | (h << 3));
                __nv_bfloat16 hx = __float2bfloat16(v.x), hy = __float2bfloat16(v.y);
                __nv_bfloat16 hz = __float2bfloat16(v.z), hw = __float2bfloat16(v.w);
                __nv_bfloat16 lx = __float2bfloat16(v.x - __bfloat162float(hx));
                __nv_bfloat16 ly = __float2bfloat16(v.y - __bfloat162float(hy));
                __nv_bfloat16 lz = __float2bfloat16(v.z - __bfloat162float(hz));
                __nv_bfloat16 lw = __float2bfloat16(v.w - __bfloat162float(hw));
                uint2 uh, ul;
                uh.x = ((uint32_t)*(uint16_t*)&hy << 16) | *(uint16_t*)&hx;
                uh.y = ((uint32_t)*(uint16_t*)&hw << 16) | *(uint16_t*)&hz;
                ul.x = ((uint32_t)*(uint16_t*)&ly << 16) | *(uint16_t*)&lx;
                ul.y = ((uint32_t)*(uint16_t*)&lw << 16) | *(uint16_t*)&lz;
                *(uint2*)(Ahi + off) = uh;
                *(uint2*)(Alo + off) = ul;
            }
        }
        asm volatile("cp.async.wait_group 0;\n");
        __syncthreads();

        #pragma unroll
        for (int ks = 0; ks < 8; ++ks) {
            uint32_t ah[2][4], al[2][4];
            #pragma unroll
            for (int mt = 0; mt < 2; ++mt) {
                int r = wm * 32 + mt * 16 + (lane & 15);
                int c = ks * 2 + (lane >> 4);
                uint32_t sw = r * 256 + ((c ^ ((r & 7) << 1)) << 4);
                asm volatile("ldmatrix.sync.aligned.m8n8.x4.shared.b16 {%0,%1,%2,%3}, [%4];\n"
                    : "=r"(ah[mt][0]), "=r"(ah[mt][1]), "=r"(ah[mt][2]), "=r"(ah[mt][3])
                    : "r"(ahi0 + sw));
                asm volatile("ldmatrix.sync.aligned.m8n8.x4.shared.b16 {%0,%1,%2,%3}, [%4];\n"
                    : "=r"(al[mt][0]), "=r"(al[mt][1]), "=r"(al[mt][2]), "=r"(al[mt][3])
                    : "r"(alo0 + sw));
            }
            #pragma unroll
            for (int nt = 0; nt < 4; ++nt) {
                int r = ks * 16 + (lane & 15);
                int c = wn * 4 + nt;
                uint32_t sw = r * 256 + ((c ^ ((r & 7) << 1)) << 4);
                uint32_t bh0, bh1, bl0, bl1;
                asm volatile("ldmatrix.sync.aligned.m8n8.x2.trans.shared.b16 {%0,%1}, [%2];\n"
                    : "=r"(bh0), "=r"(bh1) : "r"(whi0 + sw));
                asm volatile("ldmatrix.sync.aligned.m8n8.x2.trans.shared.b16 {%0,%1}, [%2];\n"
                    : "=r"(bl0), "=r"(bl1) : "r"(wlo0 + sw));
                #pragma unroll
                for (int mt = 0; mt < 2; ++mt) {
                    asm volatile(
                        "mma.sync.aligned.m16n8k16.row.col.f32.bf16.bf16.f32 "
                        "{%0,%1,%2,%3}, {%4,%5,%6,%7}, {%8,%9}, {%0,%1,%2,%3};\n"
                        : "+f"(acc[mt][nt][0]), "+f"(acc[mt][nt][1]),
                          "+f"(acc[mt][nt][2]), "+f"(acc[mt][nt][3])
                        : "r"(ah[mt][0]), "r"(ah[mt][1]), "r"(ah[mt][2]), "r"(ah[mt][3]),
                          "r"(bh0), "r"(bh1));
                    asm volatile(
                        "mma.sync.aligned.m16n8k16.row.col.f32.bf16.bf16.f32 "
                        "{%0,%1,%2,%3}, {%4,%5,%6,%7}, {%8,%9}, {%0,%1,%2,%3};\n"
                        : "+f"(acc[mt][nt][0]), "+f"(acc[mt][nt][1]),
                          "+f"(acc[mt][nt][2]), "+f"(acc[mt][nt][3])
                        : "r"(al[mt][0]), "r"(al[mt][1]), "r"(al[mt][2]), "r"(al[mt][3]),
                          "r"(bh0), "r"(bh1));
                    asm volatile(
                        "mma.sync.aligned.m16n8k16.row.col.f32.bf16.bf16.f32 "
                        "{%0,%1,%2,%3}, {%4,%5,%6,%7}, {%8,%9}, {%0,%1,%2,%3};\n"
                        : "+f"(acc[mt][nt][0]), "+f"(acc[mt][nt][1]),
                          "+f"(acc[mt][nt][2]), "+f"(acc[mt][nt][3])
                        : "r"(ah[mt][0]), "r"(ah[mt][1]), "r"(ah[mt][2]), "r"(ah[mt][3]),
                          "r"(bl0), "r"(bl1));
                }
            }
        }
        if (half == 0) __syncthreads();   // protect smem reuse for half 1
    }

    // Epilogue: bias + relu -> fp32 out (+ optional bf16 g_featb)
    #pragma unroll
    for (int mt = 0; mt < 2; ++mt) {
        int r0 = m0 + wm * 32 + mt * 16 + (lane >> 2);
        #pragma unroll
        for (int nt = 0; nt < 4; ++nt) {
            int c0 = wn * 32 + nt * 8 + (lane & 3) * 2;
            float bv0 = __ldg(&bias[c0]);
            float bv1 = __ldg(&bias[c0 + 1]);
            float o00 = fmaxf(acc[mt][nt][0] + bv0, 0.f);
            float o01 = fmaxf(acc[mt][nt][1] + bv1, 0.f);
            float o10 = fmaxf(acc[mt][nt][2] + bv0, 0.f);
            float o11 = fmaxf(acc[mt][nt][3] + bv1, 0.f);
            *(float2*)(out + (size_t)r0 * FDIM + c0)       = make_float2(o00, o01);
            *(float2*)(out + (size_t)(r0 + 8) * FDIM + c0) = make_float2(o10, o11);
            if (write_bf16) {
                __nv_bfloat162 p0 = __float22bfloat162_rn(make_float2(o00, o01));
                __nv_bfloat162 p1 = __float22bfloat162_rn(make_float2(o10, o11));
                *(__nv_bfloat162*)(g_featb + (size_t)r0 * FDIM + c0)       = p0;
                *(__nv_bfloat162*)(g_featb + (size_t)(r0 + 8) * FDIM + c0) = p1;
            }
        }
    }
}

// ---------------------------------------------------------------------------
// logits = h2 @ Wl + bl ; log_probs = logits - logsumexp(logits)
// ---------------------------------------------------------------------------
__global__ void __launch_bounds__(128)
classifier_kernel(const float* __restrict__ H,
                  const float* __restrict__ Wl,
                  const float* __restrict__ bl,
                  float* __restrict__ logp,
                  float* __restrict__ logits) {
    extern __shared__ float sh[];
    float* Hs  = sh;                  // 128*129
    float* Wls = sh + 128 * 129;      // 128*40
    float* bls = Wls + 128 * NCLS;    // 40
    const int t = threadIdx.x;
    const int row0 = blockIdx.x * 128;

    for (int j = 0; j < 128; ++j)
        Hs[j * 129 + t] = H[(size_t)(row0 + j) * FDIM + t];
    for (int idx = t; idx < 128 * NCLS; idx += 128)
        Wls[idx] = Wl[idx];
    if (t < NCLS) bls[t] = bl[t];
    __syncthreads();

    float acc[NCLS];
    #pragma unroll
    for (int c = 0; c < NCLS; ++c) acc[c] = bls[c];

    const float* hr = &Hs[t * 129];
    #pragma unroll 4
    for (int k = 0; k < FDIM; ++k) {
        float xv = hr[k];
        #pragma unroll
        for (int c = 0; c < NCLS; c += 4) {
            float4 w = *(const float4*)&Wls[k * NCLS + c];
            acc[c + 0] = fmaf(xv, w.x, acc[c + 0]);
            acc[c + 1] = fmaf(xv, w.y, acc[c + 1]);
            acc[c + 2] = fmaf(xv, w.z, acc[c + 2]);
            acc[c + 3] = fmaf(xv, w.w, acc[c + 3]);
        }
    }

    float m = acc[0];
    #pragma unroll
    for (int c = 1; c < NCLS; ++c) m = fmaxf(m, acc[c]);
    float s = 0.f;
    #pragma unroll
    for (int c = 0; c < NCLS; ++c) s += __expf(acc[c] - m);
    float lse = m + __logf(s);

    size_t ro = (size_t)(row0 + t) * NCLS;
    #pragma unroll
    for (int c = 0; c < NCLS; ++c) {
        logits[ro + c] = acc[c];
        logp[ro + c]   = acc[c] - lse;
    }
}

// ---------------------------------------------------------------------------
extern "C" void kernel_launch(void* const* d_in, const int* in_sizes, int n_in,
                              void* d_out, int out_size) {
    (void)in_sizes; (void)n_in; (void)out_size;
    const float* x   = (const float*)d_in[0];
    const float* adj = (const float*)d_in[1];
    const float* W1  = (const float*)d_in[2];
    const float* b1  = (const float*)d_in[3];
    const float* W2  = (const float*)d_in[4];
    const float* b2  = (const float*)d_in[5];
    const float* Wl  = (const float*)d_in[6];
    const float* bl  = (const float*)d_in[7];

    float* out    = (float*)d_out;
    float* logp   = out;                                  // [N, 40]
    float* h1     = logp + (size_t)N_NODES * NCLS;        // [N, 128]
    float* h2     = h1 + (size_t)N_NODES * FDIM;          // [N, 128]
    float* logits = h2 + (size_t)N_NODES * FDIM;          // [N, 40]

    const int cls_smem  = (128 * 129 + 128 * NCLS + NCLS) * (int)sizeof(float);
    const int spmm_smem = STAGES * (8192 + 16384);   // 96 KB
    const int lin_smem  = 16384 * 2 + 32768 * 2;     // 96 KB
    cudaFuncSetAttribute(spmm_kernel<1>, cudaFuncAttributeMaxDynamicSharedMemorySize, spmm_smem);
    cudaFuncSetAttribute(spmm_kernel<2>, cudaFuncAttributeMaxDynamicSharedMemorySize, spmm_smem);
    cudaFuncSetAttribute(sage_linear_tc, cudaFuncAttributeMaxDynamicSharedMemorySize, lin_smem);
    cudaFuncSetAttribute(classifier_kernel, cudaFuncAttributeMaxDynamicSharedMemorySize, cls_smem);

    // 0) W1/W2 -> pre-swizzled bf16 hi/lo tiles
    prep_w_kernel<<<4, 256>>>(W1, W2);
    // 1) x -> bf16
    cvt_x_kernel<<<512, 256>>>(x);
    // 2) support = adj @ x  (also persists bf16 swizzled adj tiles)
    spmm_kernel<1><<<N_NODES / BM, 256, spmm_smem>>>(adj);
    // 3) h1 = relu([x|s]@W1 + b1)  (also emits bf16 h1 into g_featb)
    sage_linear_tc<<<N_NODES / 64, 256, lin_smem>>>(x, 0, b1, h1, 1);
    // 4) support = adj @ h1  (A from bf16 tile cache)
    spmm_kernel<2><<<N_NODES / BM, 256, spmm_smem>>>(adj);
    // 5) h2 = relu([h1|s]@W2 + b2)
    sage_linear_tc<<<N_NODES / 64, 256, lin_smem>>>(h1, 1, b2, h2, 0);
    // 6) logits + log_softmax
    classifier_kernel<<<N_NODES / 128, 128, cls_smem>>>(h2, Wl, bl, logp, logits);
}

// round 15
// speedup vs baseline: 1.2871x; 1.0220x over previous
#include <cuda_runtime.h>
#include <cuda_bf16.h>
#include <stdint.h>

#define N_NODES 16384
#define FDIM    128
#define NCLS    40

#define BM 64
#define BK 64
#define KTILES (N_NODES / BK)   // 256
#define STAGES 4

// Scratch (static device globals — no allocation allowed)
__device__ __nv_bfloat16 g_featb [(size_t)N_NODES * FDIM];      // 4 MB
// bf16 swizzled A tiles: [mtile 0..255][ktile 0..255][8192 B]  (512 MB)
__device__ unsigned char g_adjb[(size_t)256 * 256 * 8192];
// pre-swizzled W hi/lo tiles: [w 0..1][hi/lo][half 0..1][32768 B] (256 KB)
__device__ unsigned char g_Wprep[2 * 2 * 2 * 32768];

__device__ __forceinline__ uint32_t smaddr(const void* p) {
    return (uint32_t)__cvta_generic_to_shared(p);
}
__device__ __forceinline__ void mbar_init(uint32_t a, uint32_t cnt) {
    asm volatile("mbarrier.init.shared.b64 [%0], %1;" :: "r"(a), "r"(cnt) : "memory");
}
__device__ __forceinline__ void mbar_arrive(uint32_t a) {
    asm volatile("mbarrier.arrive.release.cta.shared.b64 _, [%0];" :: "r"(a) : "memory");
}
// Blocks while the barrier's phase == parity.
__device__ __forceinline__ void mbar_wait(uint32_t a, uint32_t parity) {
    uint32_t done;
    asm volatile(
        "{\n\t.reg .pred p;\n\t"
        "mbarrier.try_wait.parity.acquire.cta.shared::cta.b64 p, [%1], %2;\n\t"
        "selp.b32 %0, 1, 0, p;\n\t}"
        : "=r"(done) : "r"(a), "r"(parity) : "memory");
    if (!done) {
        asm volatile(
            "{\n\t.reg .pred P1;\n\t"
            "WAIT_LOOP_%=:\n\t"
            "mbarrier.try_wait.parity.acquire.cta.shared::cta.b64 P1, [%0], %1, 0x989680;\n\t"
            "@P1 bra.uni WAIT_DONE_%=;\n\t"
            "bra.uni WAIT_LOOP_%=;\n\t"
            "WAIT_DONE_%=:\n\t}"
            :: "r"(a), "r"(parity) : "memory");
    }
}

// ---------------------------------------------------------------------------
// Convert x (fp32) -> g_featb (bf16)
// ---------------------------------------------------------------------------
__global__ void cvt_x_kernel(const float* __restrict__ in) {
    int i = blockIdx.x * blockDim.x + threadIdx.x;
    int stride = gridDim.x * blockDim.x;
    const int n4 = N_NODES * FDIM / 4;
    const float4* in4 = (const float4*)in;
    __nv_bfloat162* ob = (__nv_bfloat162*)g_featb;
    for (; i < n4; i += stride) {
        float4 v = in4[i];
        ob[2 * i]     = __float22bfloat162_rn(make_float2(v.x, v.y));
        ob[2 * i + 1] = __float22bfloat162_rn(make_float2(v.z, v.w));
    }
}

// ---------------------------------------------------------------------------
// One-time W prep: W fp32 [256,128] -> bf16 hi/lo, pre-swizzled tile images.
// grid 4: block = (w, half). Layout matches fused epilogue's smem exactly.
// ---------------------------------------------------------------------------
__global__ void __launch_bounds__(256)
prep_w_kernel(const float* __restrict__ W1, const float* __restrict__ W2) {
    const int w    = blockIdx.x >> 1;
    const int half = blockIdx.x & 1;
    const float* W = w ? W2 : W1;
    char* dhi = (char*)g_Wprep + w * 131072 + half * 32768;
    char* dlo = (char*)g_Wprep + w * 131072 + 65536 + half * 32768;
    const int t = threadIdx.x;
    #pragma unroll
    for (int p = 0; p < 16; ++p) {
        int idx = t + p * 256;          // 0..4095
        int r = idx >> 5, af = idx & 31;
        float4 v = *(const float4*)(W + (size_t)(half * 128 + r) * FDIM + af * 4);
        int c = af >> 1, h = af & 1;
        uint32_t off = r * 256 + (((c ^ ((r & 7) << 1)) << 4) | (h << 3));
        __nv_bfloat16 hx = __float2bfloat16(v.x), hy = __float2bfloat16(v.y);
        __nv_bfloat16 hz = __float2bfloat16(v.z), hw = __float2bfloat16(v.w);
        __nv_bfloat16 lx = __float2bfloat16(v.x - __bfloat162float(hx));
        __nv_bfloat16 ly = __float2bfloat16(v.y - __bfloat162float(hy));
        __nv_bfloat16 lz = __float2bfloat16(v.z - __bfloat162float(hz));
        __nv_bfloat16 lw = __float2bfloat16(v.w - __bfloat162float(hw));
        uint2 uh, ul;
        uh.x = ((uint32_t)*(uint16_t*)&hy << 16) | *(uint16_t*)&hx;
        uh.y = ((uint32_t)*(uint16_t*)&hw << 16) | *(uint16_t*)&hz;
        ul.x = ((uint32_t)*(uint16_t*)&ly << 16) | *(uint16_t*)&lx;
        ul.y = ((uint32_t)*(uint16_t*)&lw << 16) | *(uint16_t*)&lz;
        *(uint2*)(dhi + off) = uh;
        *(uint2*)(dlo + off) = ul;
    }
}

// ---------------------------------------------------------------------------
// Fused SpMM + SAGE linear:
//   s = adj @ feat ;  h = relu([X | s] @ W + b)
// Main loop (R5-proven): warps 0-3 consume, warps 4-7 produce, 4-stage ring.
//   MODE 1: A from fp32 adj (LDG->cvt->STS) + persist bf16 tiles to g_adjb.
//   MODE 2: A tiles from g_adjb via pure linear cp.async.
// Fused epilogue: ring smem reused as {S hi/lo 32KB, X hi/lo 32KB, Wchunk
// 32KB}; 4 sequential W chunks (hi/lo x K-half), 3-term hi/lo mma (fp32-
// accurate). Consumers mma; producers stage X. h -> hout fp32 (+ optional
// bf16 h into g_featb for the next spmm).
// ---------------------------------------------------------------------------
template<int MODE>
__global__ void __launch_bounds__(256, 2)
spmm_kernel(const float* __restrict__ A,
            const float* __restrict__ Xp,
            int wsel,
            const float* __restrict__ bias,
            float* __restrict__ hout,
            int write_bf16) {
    extern __shared__ char smem[];
    char* As = smem;                         // STAGES * 8192
    char* Bs = smem + STAGES * 8192;         // STAGES * 16384
    __shared__ uint64_t bar_full[STAGES];
    __shared__ uint64_t bar_empty[STAGES];
    const uint32_t as0 = smaddr(As);
    const uint32_t bs0 = smaddr(Bs);
    const uint32_t bf0 = smaddr(&bar_full[0]);
    const uint32_t be0 = smaddr(&bar_empty[0]);

    // Epilogue smem layout (reuses the 96KB ring after the main loop)
    const uint32_t sm0  = smaddr(smem);
    const uint32_t Shi0 = sm0;            // 16KB: 64 x 128 bf16, 256B rows
    const uint32_t Slo0 = sm0 + 16384;
    const uint32_t Xhi0 = sm0 + 32768;
    const uint32_t Xlo0 = sm0 + 49152;
    const uint32_t Wbuf = sm0 + 65536;    // 32KB: one 128x128 bf16 W image

    const int t    = threadIdx.x;
    const int lane = t & 31;
    const int warp = t >> 5;
    const int m0 = blockIdx.x * BM;
    const int wm = warp & 1;       // consumer M half
    const int wn = (warp >> 1) & 1;// consumer N half

    float acc[2][8][4];            // main-loop accumulators; reused in epilogue

    if (t == 0) {
        #pragma unroll
        for (int s = 0; s < STAGES; ++s) {
            mbar_init(bf0 + s * 8, 128);   // producers arrive
            mbar_init(be0 + s * 8, 128);   // consumers arrive
        }
    }
    __syncthreads();

    if (warp >= 4) {
        // ===================== PRODUCER (warps 4-7) =====================
        const int pt = t - 128;            // 0..127
        char* gtile_base = (char*)g_adjb + (size_t)blockIdx.x * (256 * 8192);

        auto cpB = [&](int kt, int slot) {
            const char* gsrc = (const char*)(g_featb + (size_t)kt * BK * FDIM);
            const uint32_t sbase = bs0 + slot * 16384;
            #pragma unroll
            for (int p = 0; p < 8; ++p) {
                int idx = pt + p * 128;     // 0..1023
                int r = idx >> 4;           // 0..63
                int c = idx & 15;
                uint32_t soff = r * 256 + ((c ^ ((r & 7) << 1)) << 4);
                asm volatile("cp.async.cg.shared.global [%0], [%1], 16;\n"
                             :: "r"(sbase + soff), "l"(gsrc + (size_t)r * 256 + c * 16));
            }
        };

        if (MODE == 1) {
            const int ar = pt >> 4;            // 0..7
            const int af = pt & 15;
            const float* Abase = A + (size_t)m0 * N_NODES;
            float4 regA[8], regB[8];

            auto ldgA = [&](int kt, float4 (&rg)[8]) {
                const float* src = Abase + (size_t)kt * BK + af * 4;
                #pragma unroll
                for (int p = 0; p < 8; ++p) {
                    int r = p * 8 + ar;
                    rg[p] = *(const float4*)(src + (size_t)r * N_NODES);
                }
            };
            auto stsA = [&](int slot, const float4 (&rg)[8], char* gts) {
                char* dst = As + slot * 8192;
                const int c = af >> 1, h = af & 1;
                #pragma unroll
                for (int p = 0; p < 8; ++p) {
                    int r = p * 8 + ar;
                    int off = r * 128 + (((c ^ (r & 7)) << 4) | (h << 3));
                    __nv_bfloat162 lo = __float22bfloat162_rn(make_float2(rg[p].x, rg[p].y));
                    __nv_bfloat162 hi = __float22bfloat162_rn(make_float2(rg[p].z, rg[p].w));
                    uint2 v;
                    v.x = *(uint32_t*)&lo;
                    v.y = *(uint32_t*)&hi;
                    *(uint2*)(dst + off) = v;
                    asm volatile("st.global.cs.v2.b32 [%0], {%1, %2};"
                                 :: "l"(gts + off), "r"(v.x), "r"(v.y) : "memory");
                }
            };

            mbar_wait(be0 + 0, 1);
            cpB(0, 0);
            asm volatile("cp.async.commit_group;\n");
            ldgA(0, regA);

            #pragma unroll 1
            for (int tt = 0; tt < KTILES; tt += 2) {
                {
                    const int nt = tt + 1;
                    const int ns = nt & (STAGES - 1);
                    mbar_wait(be0 + ns * 8, ((nt >> 2) & 1) ^ 1);
                    cpB(nt, ns);
                    asm volatile("cp.async.commit_group;\n");
                    ldgA(nt, regB);
                    stsA(tt & (STAGES - 1), regA, gtile_base + (size_t)tt * 8192);
                    asm volatile("cp.async.wait_group 1;\n");
                    mbar_arrive(bf0 + (tt & (STAGES - 1)) * 8);
                }
                {
                    const int ct = tt + 1;
                    const int nt = tt + 2;
                    if (nt < KTILES) {
                        const int ns = nt & (STAGES - 1);
                        mbar_wait(be0 + ns * 8, ((nt >> 2) & 1) ^ 1);
                        cpB(nt, ns);
                        asm volatile("cp.async.commit_group;\n");
                        ldgA(nt, regA);
                        stsA(ct & (STAGES - 1), regB, gtile_base + (size_t)ct * 8192);
                        asm volatile("cp.async.wait_group 1;\n");
                    } else {
                        stsA(ct & (STAGES - 1), regB, gtile_base + (size_t)ct * 8192);
                        asm volatile("cp.async.wait_group 0;\n");
                    }
                    mbar_arrive(bf0 + (ct & (STAGES - 1)) * 8);
                }
            }
        } else {
            // MODE 2: A tiles are ready-made swizzled bf16 images in g_adjb.
            auto cpA2 = [&](int kt, int slot) {
                const char* src = gtile_base + (size_t)kt * 8192 + pt * 16;
                const uint32_t dst = as0 + slot * 8192 + pt * 16;
                #pragma unroll
                for (int p = 0; p < 4; ++p)
                    asm volatile("cp.async.cg.shared.global [%0], [%1], 16;\n"
                                 :: "r"(dst + p * 2048), "l"(src + p * 2048));
            };

            mbar_wait(be0 + 0, 1);
            cpA2(0, 0);
            cpB(0, 0);
            asm volatile("cp.async.commit_group;\n");

            #pragma unroll 1
            for (int tt = 0; tt < KTILES; ++tt) {
                const int nt = tt + 1;
                if (nt < KTILES) {
                    const int ns = nt & (STAGES - 1);
                    mbar_wait(be0 + ns * 8, ((nt >> 2) & 1) ^ 1);
                    cpA2(nt, ns);
                    cpB(nt, ns);
                    asm volatile("cp.async.commit_group;\n");
                    asm volatile("cp.async.wait_group 1;\n");
                } else {
                    asm volatile("cp.async.wait_group 0;\n");
                }
                mbar_arrive(bf0 + (tt & (STAGES - 1)) * 8);
            }
        }
    } else {
        // ===================== CONSUMER (warps 0-3) =====================
        #pragma unroll
        for (int i = 0; i < 2; ++i)
            #pragma unroll
            for (int j = 0; j < 8; ++j)
                #pragma unroll
                for (int k = 0; k < 4; ++k) acc[i][j][k] = 0.f;

        #pragma unroll 1
        for (int tt = 0; tt < KTILES; ++tt) {
            const int slot = tt & (STAGES - 1);
            mbar_wait(bf0 + slot * 8, (tt >> 2) & 1);
            const uint32_t ab = as0 + slot * 8192;
            const uint32_t bb = bs0 + slot * 16384;
            #pragma unroll
            for (int ks = 0; ks < 4; ++ks) {
                uint32_t a[2][4];
                #pragma unroll
                for (int mt = 0; mt < 2; ++mt) {
                    int r = wm * 32 + mt * 16 + (lane & 15);
                    int c = ks * 2 + (lane >> 4);
                    uint32_t addr = ab + r * 128 + ((c ^ (r & 7)) << 4);
                    asm volatile("ldmatrix.sync.aligned.m8n8.x4.shared.b16 {%0,%1,%2,%3}, [%4];\n"
                        : "=r"(a[mt][0]), "=r"(a[mt][1]), "=r"(a[mt][2]), "=r"(a[mt][3])
                        : "r"(addr));
                }
                uint32_t b[8][2];
                #pragma unroll
                for (int nt = 0; nt < 8; ++nt) {
                    int r = ks * 16 + (lane & 15);
                    int c = wn * 8 + nt;
                    uint32_t addr = bb + r * 256 + ((c ^ ((r & 7) << 1)) << 4);
                    asm volatile("ldmatrix.sync.aligned.m8n8.x2.trans.shared.b16 {%0,%1}, [%2];\n"
                        : "=r"(b[nt][0]), "=r"(b[nt][1]) : "r"(addr));
                }
                #pragma unroll
                for (int mt = 0; mt < 2; ++mt)
                    #pragma unroll
                    for (int nt = 0; nt < 8; ++nt) {
                        asm volatile(
                            "mma.sync.aligned.m16n8k16.row.col.f32.bf16.bf16.f32 "
                            "{%0,%1,%2,%3}, {%4,%5,%6,%7}, {%8,%9}, {%0,%1,%2,%3};\n"
                            : "+f"(acc[mt][nt][0]), "+f"(acc[mt][nt][1]),
                              "+f"(acc[mt][nt][2]), "+f"(acc[mt][nt][3])
                            : "r"(a[mt][0]), "r"(a[mt][1]), "r"(a[mt][2]), "r"(a[mt][3]),
                              "r"(b[nt][0]), "r"(b[nt][1]));
                    }
            }
            mbar_arrive(be0 + slot * 8);
        }
    }

    // ======================= FUSED LINEAR EPILOGUE =========================
    __syncthreads();   // main loop fully drained; ring smem free for reuse

    if (warp < 4) {
        // Consumers: write S tile (acc) to smem as bf16 hi/lo, swizzled
        #pragma unroll
        for (int mt = 0; mt < 2; ++mt) {
            #pragma unroll
            for (int nt = 0; nt < 8; ++nt) {
                int r0 = wm * 32 + mt * 16 + (lane >> 2);
                int cc = wn * 8 + nt;                    // 16B chunk index
                uint32_t wb = ((uint32_t)(lane & 3)) * 4; // byte within chunk
                #pragma unroll
                for (int q = 0; q < 2; ++q) {
                    int r = r0 + q * 8;
                    float v0 = acc[mt][nt][q * 2 + 0];
                    float v1 = acc[mt][nt][q * 2 + 1];
                    __nv_bfloat16 h0 = __float2bfloat16(v0);
                    __nv_bfloat16 h1b = __float2bfloat16(v1);
                    __nv_bfloat16 l0 = __float2bfloat16(v0 - __bfloat162float(h0));
                    __nv_bfloat16 l1 = __float2bfloat16(v1 - __bfloat162float(h1b));
                    uint32_t ph = ((uint32_t)*(uint16_t*)&h1b << 16) | *(uint16_t*)&h0;
                    uint32_t pl = ((uint32_t)*(uint16_t*)&l1 << 16) | *(uint16_t*)&l0;
                    uint32_t off = r * 256 + ((cc ^ ((r & 7) << 1)) << 4) + wb;
                    asm volatile("st.shared.b32 [%0], %1;" :: "r"(Shi0 + off), "r"(ph) : "memory");
                    asm volatile("st.shared.b32 [%0], %1;" :: "r"(Slo0 + off), "r"(pl) : "memory");
                }
            }
        }
    } else {
        // Producers: stage X rows (fp32 -> bf16 hi/lo, swizzled)
        const int pt = t - 128;
        const float* src = Xp + (size_t)m0 * FDIM;
        #pragma unroll
        for (int p = 0; p < 16; ++p) {
            int idx = pt + p * 128;         // 0..2047
            int r = idx >> 5, af = idx & 31;
            float4 v = *(const float4*)(src + (size_t)r * FDIM + af * 4);
            int c = af >> 1, h = af & 1;
            uint32_t off = r * 256 + (((c ^ ((r & 7) << 1)) << 4) | (h << 3));
            __nv_bfloat16 hx = __float2bfloat16(v.x), hy = __float2bfloat16(v.y);
            __nv_bfloat16 hz = __float2bfloat16(v.z), hw = __float2bfloat16(v.w);
            __nv_bfloat16 lx = __float2bfloat16(v.x - __bfloat162float(hx));
            __nv_bfloat16 ly = __float2bfloat16(v.y - __bfloat162float(hy));
            __nv_bfloat16 lz = __float2bfloat16(v.z - __bfloat162float(hz));
            __nv_bfloat16 lw = __float2bfloat16(v.w - __bfloat162float(hw));
            uint2 uh, ul;
            uh.x = ((uint32_t)*(uint16_t*)&hy << 16) | *(uint16_t*)&hx;
            uh.y = ((uint32_t)*(uint16_t*)&hw << 16) | *(uint16_t*)&hz;
            ul.x = ((uint32_t)*(uint16_t*)&ly << 16) | *(uint16_t*)&lx;
            ul.y = ((uint32_t)*(uint16_t*)&lw << 16) | *(uint16_t*)&lz;
            asm volatile("st.shared.v2.b32 [%0], {%1,%2};" :: "r"(Xhi0 + off), "r"(uh.x), "r"(uh.y) : "memory");
            asm volatile("st.shared.v2.b32 [%0], {%1,%2};" :: "r"(Xlo0 + off), "r"(ul.x), "r"(ul.y) : "memory");
        }
    }

    // Stage W chunk 0 (all 256 threads): Whi of K-half 0
    {
        const char* wsrc = (const char*)g_Wprep + wsel * 131072;  // hilo=0, half=0
        #pragma unroll
        for (int p = 0; p < 8; ++p) {
            int idx = t + p * 256;          // 0..2047 16B chunks
            asm volatile("cp.async.cg.shared.global [%0], [%1], 16;\n"
                :: "r"(Wbuf + idx * 16), "l"(wsrc + idx * 16));
        }
        asm volatile("cp.async.commit_group;\n");
        asm volatile("cp.async.wait_group 0;\n");
    }
    __syncthreads();

    // Zero linear accumulators (reuse acc)
    #pragma unroll
    for (int i = 0; i < 2; ++i)
        #pragma unroll
        for (int j = 0; j < 8; ++j)
            #pragma unroll
            for (int k = 0; k < 4; ++k) acc[i][j][k] = 0.f;

    // 4 W chunks: (hi,half0), (lo,half0), (hi,half1), (lo,half1)
    #pragma unroll 1
    for (int chunk = 0; chunk < 4; ++chunk) {
        const int half = chunk >> 1;
        const int isLo = chunk & 1;
        const int npass = isLo ? 1 : 2;
        const uint32_t abase0 = half ? Shi0 : Xhi0;
        const uint32_t abase1 = half ? Slo0 : Xlo0;

        if (warp < 4) {
            #pragma unroll 1
            for (int pass = 0; pass < npass; ++pass) {
                const uint32_t ab = pass ? abase1 : abase0;
                #pragma unroll
                for (int ks = 0; ks < 8; ++ks) {
                    uint32_t a[2][4];
                    #pragma unroll
                    for (int mt = 0; mt < 2; ++mt) {
                        int r = wm * 32 + mt * 16 + (lane & 15);
                        int c = ks * 2 + (lane >> 4);
                        uint32_t sw = r * 256 + ((c ^ ((r & 7) << 1)) << 4);
                        asm volatile("ldmatrix.sync.aligned.m8n8.x4.shared.b16 {%0,%1,%2,%3}, [%4];\n"
                            : "=r"(a[mt][0]), "=r"(a[mt][1]), "=r"(a[mt][2]), "=r"(a[mt][3])
                            : "r"(ab + sw));
                    }
                    #pragma unroll
                    for (int nt = 0; nt < 8; ++nt) {
                        uint32_t b0, b1;
                        int r = ks * 16 + (lane & 15);
                        int c = wn * 8 + nt;
                        uint32_t sw = r * 256 + ((c ^ ((r & 7) << 1)) << 4);
                        asm volatile("ldmatrix.sync.aligned.m8n8.x2.trans.shared.b16 {%0,%1}, [%2];\n"
                            : "=r"(b0), "=r"(b1) : "r"(Wbuf + sw));
                        #pragma unroll
                        for (int mt = 0; mt < 2; ++mt) {
                            asm volatile(
                                "mma.sync.aligned.m16n8k16.row.col.f32.bf16.bf16.f32 "
                                "{%0,%1,%2,%3}, {%4,%5,%6,%7}, {%8,%9}, {%0,%1,%2,%3};\n"
                                : "+f"(acc[mt][nt][0]), "+f"(acc[mt][nt][1]),
                                  "+f"(acc[mt][nt][2]), "+f"(acc[mt][nt][3])
                                : "r"(a[mt][0]), "r"(a[mt][1]), "r"(a[mt][2]), "r"(a[mt][3]),
                                  "r"(b0), "r"(b1));
                        }
                    }
                }
            }
        }
        __syncthreads();   // mma done before Wbuf overwrite
        if (chunk < 3) {
            const int nh = (chunk + 1) >> 1, nl = (chunk + 1) & 1;
            const char* wsrc = (const char*)g_Wprep + wsel * 131072 + nl * 65536 + nh * 32768;
            #pragma unroll
            for (int p = 0; p < 8; ++p) {
                int idx = t + p * 256;
                asm volatile("cp.async.cg.shared.global [%0], [%1], 16;\n"
                    :: "r"(Wbuf + idx * 16), "l"(wsrc + idx * 16));
            }
            asm volatile("cp.async.commit_group;\n");
            asm volatile("cp.async.wait_group 0;\n");
            __syncthreads();
        }
    }

    // Final write: bias + relu -> hout fp32 (+ optional bf16 g_featb)
    if (warp < 4) {
        #pragma unroll
        for (int mt = 0; mt < 2; ++mt) {
            int r0 = m0 + wm * 32 + mt * 16 + (lane >> 2);
            #pragma unroll
            for (int nt = 0; nt < 8; ++nt) {
                int c0 = wn * 64 + nt * 8 + (lane & 3) * 2;
                float bv0 = __ldg(&bias[c0]);
                float bv1 = __ldg(&bias[c0 + 1]);
                float o00 = fmaxf(acc[mt][nt][0] + bv0, 0.f);
                float o01 = fmaxf(acc[mt][nt][1] + bv1, 0.f);
                float o10 = fmaxf(acc[mt][nt][2] + bv0, 0.f);
                float o11 = fmaxf(acc[mt][nt][3] + bv1, 0.f);
                *(float2*)(hout + (size_t)r0 * FDIM + c0)       = make_float2(o00, o01);
                *(float2*)(hout + (size_t)(r0 + 8) * FDIM + c0) = make_float2(o10, o11);
                if (write_bf16) {
                    __nv_bfloat162 p0 = __float22bfloat162_rn(make_float2(o00, o01));
                    __nv_bfloat162 p1 = __float22bfloat162_rn(make_float2(o10, o11));
                    *(__nv_bfloat162*)(g_featb + (size_t)r0 * FDIM + c0)       = p0;
                    *(__nv_bfloat162*)(g_featb + (size_t)(r0 + 8) * FDIM + c0) = p1;
                }
            }
        }
    }
}

// ---------------------------------------------------------------------------
// logits = h2 @ Wl + bl ; log_probs = logits - logsumexp(logits)
// ---------------------------------------------------------------------------
__global__ void __launch_bounds__(128)
classifier_kernel(const float* __restrict__ H,
                  const float* __restrict__ Wl,
                  const float* __restrict__ bl,
                  float* __restrict__ logp,
                  float* __restrict__ logits) {
    extern __shared__ float sh[];
    float* Hs  = sh;                  // 128*129
    float* Wls = sh + 128 * 129;      // 128*40
    float* bls = Wls + 128 * NCLS;    // 40
    const int t = threadIdx.x;
    const int row0 = blockIdx.x * 128;

    for (int j = 0; j < 128; ++j)
        Hs[j * 129 + t] = H[(size_t)(row0 + j) * FDIM + t];
    for (int idx = t; idx < 128 * NCLS; idx += 128)
        Wls[idx] = Wl[idx];
    if (t < NCLS) bls[t] = bl[t];
    __syncthreads();

    float acc[NCLS];
    #pragma unroll
    for (int c = 0; c < NCLS; ++c) acc[c] = bls[c];

    const float* hr = &Hs[t * 129];
    #pragma unroll 4
    for (int k = 0; k < FDIM; ++k) {
        float xv = hr[k];
        #pragma unroll
        for (int c = 0; c < NCLS; c += 4) {
            float4 w = *(const float4*)&Wls[k * NCLS + c];
            acc[c + 0] = fmaf(xv, w.x, acc[c + 0]);
            acc[c + 1] = fmaf(xv, w.y, acc[c + 1]);
            acc[c + 2] = fmaf(xv, w.z, acc[c + 2]);
            acc[c + 3] = fmaf(xv, w.w, acc[c + 3]);
        }
    }

    float m = acc[0];
    #pragma unroll
    for (int c = 1; c < NCLS; ++c) m = fmaxf(m, acc[c]);
    float s = 0.f;
    #pragma unroll
    for (int c = 0; c < NCLS; ++c) s += __expf(acc[c] - m);
    float lse = m + __logf(s);

    size_t ro = (size_t)(row0 + t) * NCLS;
    #pragma unroll
    for (int c = 0; c < NCLS; ++c) {
        logits[ro + c] = acc[c];
        logp[ro + c]   = acc[c] - lse;
    }
}

// ---------------------------------------------------------------------------
extern "C" void kernel_launch(void* const* d_in, const int* in_sizes, int n_in,
                              void* d_out, int out_size) {
    (void)in_sizes; (void)n_in; (void)out_size;
    const float* x   = (const float*)d_in[0];
    const float* adj = (const float*)d_in[1];
    const float* W1  = (const float*)d_in[2];
    const float* b1  = (const float*)d_in[3];
    const float* W2  = (const float*)d_in[4];
    const float* b2  = (const float*)d_in[5];
    const float* Wl  = (const float*)d_in[6];
    const float* bl  = (const float*)d_in[7];

    float* out    = (float*)d_out;
    float* logp   = out;                                  // [N, 40]
    float* h1     = logp + (size_t)N_NODES * NCLS;        // [N, 128]
    float* h2     = h1 + (size_t)N_NODES * FDIM;          // [N, 128]
    float* logits = h2 + (size_t)N_NODES * FDIM;          // [N, 40]

    const int cls_smem  = (128 * 129 + 128 * NCLS + NCLS) * (int)sizeof(float);
    const int spmm_smem = STAGES * (8192 + 16384);   // 96 KB
    cudaFuncSetAttribute(spmm_kernel<1>, cudaFuncAttributeMaxDynamicSharedMemorySize, spmm_smem);
    cudaFuncSetAttribute(spmm_kernel<2>, cudaFuncAttributeMaxDynamicSharedMemorySize, spmm_smem);
    cudaFuncSetAttribute(classifier_kernel, cudaFuncAttributeMaxDynamicSharedMemorySize, cls_smem);

    // 0) W1/W2 -> pre-swizzled bf16 hi/lo tiles
    prep_w_kernel<<<4, 256>>>(W1, W2);
    // 1) x -> bf16
    cvt_x_kernel<<<512, 256>>>(x);
    // 2) s = adj @ x ; h1 = relu([x|s]@W1+b1)  (persists bf16 adj tiles + bf16 h1)
    spmm_kernel<1><<<N_NODES / BM, 256, spmm_smem>>>(adj, x, 0, b1, h1, 1);
    // 3) s = adj @ h1 ; h2 = relu([h1|s]@W2+b2)  (A from bf16 tile cache)
    spmm_kernel<2><<<N_NODES / BM, 256, spmm_smem>>>(adj, h1, 1, b2, h2, 0);
    // 4) logits + log_softmax
    classifier_kernel<<<N_NODES / 128, 128, cls_smem>>>(h2, Wl, bl, logp, logits);
}

// round 16
// speedup vs baseline: 1.2873x; 1.0001x over previous
#include <cuda_runtime.h>
#include <cuda_bf16.h>
#include <stdint.h>

#define N_NODES 16384
#define FDIM    128
#define NCLS    40

#define BM 64
#define BK 64
#define KTILES (N_NODES / BK)   // 256
#define STAGES 4

// Scratch (static device globals — no allocation allowed)
__device__ __nv_bfloat16 g_featb [(size_t)N_NODES * FDIM];      // 4 MB
// pre-swizzled W hi/lo tiles: [w 0..1][hi/lo][half 0..1][32768 B] (256 KB)
__device__ unsigned char g_Wprep[2 * 2 * 2 * 32768];

__device__ __forceinline__ uint32_t smaddr(const void* p) {
    return (uint32_t)__cvta_generic_to_shared(p);
}
__device__ __forceinline__ void mbar_init(uint32_t a, uint32_t cnt) {
    asm volatile("mbarrier.init.shared.b64 [%0], %1;" :: "r"(a), "r"(cnt) : "memory");
}
__device__ __forceinline__ void mbar_arrive(uint32_t a) {
    asm volatile("mbarrier.arrive.release.cta.shared.b64 _, [%0];" :: "r"(a) : "memory");
}
// Blocks while the barrier's phase == parity.
__device__ __forceinline__ void mbar_wait(uint32_t a, uint32_t parity) {
    uint32_t done;
    asm volatile(
        "{\n\t.reg .pred p;\n\t"
        "mbarrier.try_wait.parity.acquire.cta.shared::cta.b64 p, [%1], %2;\n\t"
        "selp.b32 %0, 1, 0, p;\n\t}"
        : "=r"(done) : "r"(a), "r"(parity) : "memory");
    if (!done) {
        asm volatile(
            "{\n\t.reg .pred P1;\n\t"
            "WAIT_LOOP_%=:\n\t"
            "mbarrier.try_wait.parity.acquire.cta.shared::cta.b64 P1, [%0], %1, 0x989680;\n\t"
            "@P1 bra.uni WAIT_DONE_%=;\n\t"
            "bra.uni WAIT_LOOP_%=;\n\t"
            "WAIT_DONE_%=:\n\t}"
            :: "r"(a), "r"(parity) : "memory");
    }
}

// ---------------------------------------------------------------------------
// Convert x (fp32) -> g_featb (bf16)
// ---------------------------------------------------------------------------
__global__ void cvt_x_kernel(const float* __restrict__ in) {
    int i = blockIdx.x * blockDim.x + threadIdx.x;
    int stride = gridDim.x * blockDim.x;
    const int n4 = N_NODES * FDIM / 4;
    const float4* in4 = (const float4*)in;
    __nv_bfloat162* ob = (__nv_bfloat162*)g_featb;
    for (; i < n4; i += stride) {
        float4 v = in4[i];
        ob[2 * i]     = __float22bfloat162_rn(make_float2(v.x, v.y));
        ob[2 * i + 1] = __float22bfloat162_rn(make_float2(v.z, v.w));
    }
}

// ---------------------------------------------------------------------------
// One-time W prep: W fp32 [256,128] -> bf16 hi/lo, pre-swizzled tile images.
// grid 4: block = (w, half). Layout matches fused epilogue's smem exactly.
// ---------------------------------------------------------------------------
__global__ void __launch_bounds__(256)
prep_w_kernel(const float* __restrict__ W1, const float* __restrict__ W2) {
    const int w    = blockIdx.x >> 1;
    const int half = blockIdx.x & 1;
    const float* W = w ? W2 : W1;
    char* dhi = (char*)g_Wprep + w * 131072 + half * 32768;
    char* dlo = (char*)g_Wprep + w * 131072 + 65536 + half * 32768;
    const int t = threadIdx.x;
    #pragma unroll
    for (int p = 0; p < 16; ++p) {
        int idx = t + p * 256;          // 0..4095
        int r = idx >> 5, af = idx & 31;
        float4 v = *(const float4*)(W + (size_t)(half * 128 + r) * FDIM + af * 4);
        int c = af >> 1, h = af & 1;
        uint32_t off = r * 256 + (((c ^ ((r & 7) << 1)) << 4) | (h << 3));
        __nv_bfloat16 hx = __float2bfloat16(v.x), hy = __float2bfloat16(v.y);
        __nv_bfloat16 hz = __float2bfloat16(v.z), hw = __float2bfloat16(v.w);
        __nv_bfloat16 lx = __float2bfloat16(v.x - __bfloat162float(hx));
        __nv_bfloat16 ly = __float2bfloat16(v.y - __bfloat162float(hy));
        __nv_bfloat16 lz = __float2bfloat16(v.z - __bfloat162float(hz));
        __nv_bfloat16 lw = __float2bfloat16(v.w - __bfloat162float(hw));
        uint2 uh, ul;
        uh.x = ((uint32_t)*(uint16_t*)&hy << 16) | *(uint16_t*)&hx;
        uh.y = ((uint32_t)*(uint16_t*)&hw << 16) | *(uint16_t*)&hz;
        ul.x = ((uint32_t)*(uint16_t*)&ly << 16) | *(uint16_t*)&lx;
        ul.y = ((uint32_t)*(uint16_t*)&lw << 16) | *(uint16_t*)&lz;
        *(uint2*)(dhi + off) = uh;
        *(uint2*)(dlo + off) = ul;
    }
}

// ---------------------------------------------------------------------------
// Fused SpMM + SAGE linear:
//   s = adj @ feat ;  h = relu([X | s] @ W + b)
// Main loop (R5/R12-proven): warps 0-3 consume, warps 4-7 produce, 4-stage
// ring; A from fp32 adj (LDG -> cvt bf16 -> SW128 STS, 2-deep reg staging);
// B via cp.async.cg from g_featb (L2-hot). NO adj tile cache (R15 showed the
// STG stream costs spmm1 more than the halved read saves spmm2).
// Fused epilogue: ring smem reused as {S hi/lo 32KB, X hi/lo 32KB, Wchunk
// 32KB}; 4 sequential W chunks (hi/lo x K-half), 3-term hi/lo mma (fp32-
// accurate). h -> hout fp32 (+ optional bf16 h into g_featb for next spmm).
// ---------------------------------------------------------------------------
__global__ void __launch_bounds__(256, 2)
spmm_fused_kernel(const float* __restrict__ A,
                  const float* __restrict__ Xp,
                  int wsel,
                  const float* __restrict__ bias,
                  float* __restrict__ hout,
                  int write_bf16) {
    extern __shared__ char smem[];
    char* As = smem;                         // STAGES * 8192
    char* Bs = smem + STAGES * 8192;         // STAGES * 16384
    __shared__ uint64_t bar_full[STAGES];
    __shared__ uint64_t bar_empty[STAGES];
    const uint32_t as0 = smaddr(As);
    const uint32_t bs0 = smaddr(Bs);
    const uint32_t bf0 = smaddr(&bar_full[0]);
    const uint32_t be0 = smaddr(&bar_empty[0]);

    // Epilogue smem layout (reuses the 96KB ring after the main loop)
    const uint32_t sm0  = smaddr(smem);
    const uint32_t Shi0 = sm0;            // 16KB: 64 x 128 bf16, 256B rows
    const uint32_t Slo0 = sm0 + 16384;
    const uint32_t Xhi0 = sm0 + 32768;
    const uint32_t Xlo0 = sm0 + 49152;
    const uint32_t Wbuf = sm0 + 65536;    // 32KB: one 128x128 bf16 W image

    const int t    = threadIdx.x;
    const int lane = t & 31;
    const int warp = t >> 5;
    const int m0 = blockIdx.x * BM;
    const int wm = warp & 1;       // consumer M half
    const int wn = (warp >> 1) & 1;// consumer N half

    float acc[2][8][4];            // main-loop accumulators; reused in epilogue

    if (t == 0) {
        #pragma unroll
        for (int s = 0; s < STAGES; ++s) {
            mbar_init(bf0 + s * 8, 128);   // producers arrive
            mbar_init(be0 + s * 8, 128);   // consumers arrive
        }
    }
    __syncthreads();

    if (warp >= 4) {
        // ===================== PRODUCER (warps 4-7) =====================
        const int pt = t - 128;            // 0..127
        const int ar = pt >> 4;            // 0..7
        const int af = pt & 15;            // float4 slot within 64-float row
        const float* Abase = A + (size_t)m0 * N_NODES;
        float4 regA[8], regB[8];

        auto cpB = [&](int kt, int slot) {
            const char* gsrc = (const char*)(g_featb + (size_t)kt * BK * FDIM);
            const uint32_t sbase = bs0 + slot * 16384;
            #pragma unroll
            for (int p = 0; p < 8; ++p) {
                int idx = pt + p * 128;     // 0..1023
                int r = idx >> 4;           // 0..63
                int c = idx & 15;
                uint32_t soff = r * 256 + ((c ^ ((r & 7) << 1)) << 4);
                asm volatile("cp.async.cg.shared.global [%0], [%1], 16;\n"
                             :: "r"(sbase + soff), "l"(gsrc + (size_t)r * 256 + c * 16));
            }
        };
        auto ldgA = [&](int kt, float4 (&rg)[8]) {
            const float* src = Abase + (size_t)kt * BK + af * 4;
            #pragma unroll
            for (int p = 0; p < 8; ++p) {
                int r = p * 8 + ar;
                rg[p] = *(const float4*)(src + (size_t)r * N_NODES);
            }
        };
        auto stsA = [&](int slot, const float4 (&rg)[8]) {
            char* dst = As + slot * 8192;
            const int c = af >> 1, h = af & 1;
            #pragma unroll
            for (int p = 0; p < 8; ++p) {
                int r = p * 8 + ar;
                int off = r * 128 + (((c ^ (r & 7)) << 4) | (h << 3));
                __nv_bfloat162 lo = __float22bfloat162_rn(make_float2(rg[p].x, rg[p].y));
                __nv_bfloat162 hi = __float22bfloat162_rn(make_float2(rg[p].z, rg[p].w));
                uint2 v;
                v.x = *(uint32_t*)&lo;
                v.y = *(uint32_t*)&hi;
                *(uint2*)(dst + off) = v;
            }
        };

        // prologue: tile 0 into flight
        mbar_wait(be0 + 0, 1);
        cpB(0, 0);
        asm volatile("cp.async.commit_group;\n");
        ldgA(0, regA);

        #pragma unroll 1
        for (int tt = 0; tt < KTILES; tt += 2) {
            { // even tile tt (data in regA), prefetch tt+1 into regB
                const int nt = tt + 1;
                const int ns = nt & (STAGES - 1);
                mbar_wait(be0 + ns * 8, ((nt >> 2) & 1) ^ 1);
                cpB(nt, ns);
                asm volatile("cp.async.commit_group;\n");
                ldgA(nt, regB);
                stsA(tt & (STAGES - 1), regA);
                asm volatile("cp.async.wait_group 1;\n");
                mbar_arrive(bf0 + (tt & (STAGES - 1)) * 8);
            }
            { // odd tile tt+1 (data in regB), prefetch tt+2 into regA
                const int ct = tt + 1;
                const int nt = tt + 2;
                if (nt < KTILES) {
                    const int ns = nt & (STAGES - 1);
                    mbar_wait(be0 + ns * 8, ((nt >> 2) & 1) ^ 1);
                    cpB(nt, ns);
                    asm volatile("cp.async.commit_group;\n");
                    ldgA(nt, regA);
                    stsA(ct & (STAGES - 1), regB);
                    asm volatile("cp.async.wait_group 1;\n");
                } else {
                    stsA(ct & (STAGES - 1), regB);
                    asm volatile("cp.async.wait_group 0;\n");
                }
                mbar_arrive(bf0 + (ct & (STAGES - 1)) * 8);
            }
        }
    } else {
        // ===================== CONSUMER (warps 0-3) =====================
        #pragma unroll
        for (int i = 0; i < 2; ++i)
            #pragma unroll
            for (int j = 0; j < 8; ++j)
                #pragma unroll
                for (int k = 0; k < 4; ++k) acc[i][j][k] = 0.f;

        #pragma unroll 1
        for (int tt = 0; tt < KTILES; ++tt) {
            const int slot = tt & (STAGES - 1);
            mbar_wait(bf0 + slot * 8, (tt >> 2) & 1);
            const uint32_t ab = as0 + slot * 8192;
            const uint32_t bb = bs0 + slot * 16384;
            #pragma unroll
            for (int ks = 0; ks < 4; ++ks) {
                uint32_t a[2][4];
                #pragma unroll
                for (int mt = 0; mt < 2; ++mt) {
                    int r = wm * 32 + mt * 16 + (lane & 15);
                    int c = ks * 2 + (lane >> 4);
                    uint32_t addr = ab + r * 128 + ((c ^ (r & 7)) << 4);
                    asm volatile("ldmatrix.sync.aligned.m8n8.x4.shared.b16 {%0,%1,%2,%3}, [%4];\n"
                        : "=r"(a[mt][0]), "=r"(a[mt][1]), "=r"(a[mt][2]), "=r"(a[mt][3])
                        : "r"(addr));
                }
                uint32_t b[8][2];
                #pragma unroll
                for (int nt = 0; nt < 8; ++nt) {
                    int r = ks * 16 + (lane & 15);
                    int c = wn * 8 + nt;
                    uint32_t addr = bb + r * 256 + ((c ^ ((r & 7) << 1)) << 4);
                    asm volatile("ldmatrix.sync.aligned.m8n8.x2.trans.shared.b16 {%0,%1}, [%2];\n"
                        : "=r"(b[nt][0]), "=r"(b[nt][1]) : "r"(addr));
                }
                #pragma unroll
                for (int mt = 0; mt < 2; ++mt)
                    #pragma unroll
                    for (int nt = 0; nt < 8; ++nt) {
                        asm volatile(
                            "mma.sync.aligned.m16n8k16.row.col.f32.bf16.bf16.f32 "
                            "{%0,%1,%2,%3}, {%4,%5,%6,%7}, {%8,%9}, {%0,%1,%2,%3};\n"
                            : "+f"(acc[mt][nt][0]), "+f"(acc[mt][nt][1]),
                              "+f"(acc[mt][nt][2]), "+f"(acc[mt][nt][3])
                            : "r"(a[mt][0]), "r"(a[mt][1]), "r"(a[mt][2]), "r"(a[mt][3]),
                              "r"(b[nt][0]), "r"(b[nt][1]));
                    }
            }
            mbar_arrive(be0 + slot * 8);
        }
    }

    // ======================= FUSED LINEAR EPILOGUE =========================
    __syncthreads();   // main loop fully drained; ring smem free for reuse

    if (warp < 4) {
        // Consumers: write S tile (acc) to smem as bf16 hi/lo, swizzled
        #pragma unroll
        for (int mt = 0; mt < 2; ++mt) {
            #pragma unroll
            for (int nt = 0; nt < 8; ++nt) {
                int r0 = wm * 32 + mt * 16 + (lane >> 2);
                int cc = wn * 8 + nt;                    // 16B chunk index
                uint32_t wb = ((uint32_t)(lane & 3)) * 4; // byte within chunk
                #pragma unroll
                for (int q = 0; q < 2; ++q) {
                    int r = r0 + q * 8;
                    float v0 = acc[mt][nt][q * 2 + 0];
                    float v1 = acc[mt][nt][q * 2 + 1];
                    __nv_bfloat16 h0 = __float2bfloat16(v0);
                    __nv_bfloat16 h1b = __float2bfloat16(v1);
                    __nv_bfloat16 l0 = __float2bfloat16(v0 - __bfloat162float(h0));
                    __nv_bfloat16 l1 = __float2bfloat16(v1 - __bfloat162float(h1b));
                    uint32_t ph = ((uint32_t)*(uint16_t*)&h1b << 16) | *(uint16_t*)&h0;
                    uint32_t pl = ((uint32_t)*(uint16_t*)&l1 << 16) | *(uint16_t*)&l0;
                    uint32_t off = r * 256 + ((cc ^ ((r & 7) << 1)) << 4) + wb;
                    asm volatile("st.shared.b32 [%0], %1;" :: "r"(Shi0 + off), "r"(ph) : "memory");
                    asm volatile("st.shared.b32 [%0], %1;" :: "r"(Slo0 + off), "r"(pl) : "memory");
                }
            }
        }
    } else {
        // Producers: stage X rows (fp32 -> bf16 hi/lo, swizzled)
        const int pt = t - 128;
        const float* src = Xp + (size_t)m0 * FDIM;
        #pragma unroll
        for (int p = 0; p < 16; ++p) {
            int idx = pt + p * 128;         // 0..2047
            int r = idx >> 5, af = idx & 31;
            float4 v = *(const float4*)(src + (size_t)r * FDIM + af * 4);
            int c = af >> 1, h = af & 1;
            uint32_t off = r * 256 + (((c ^ ((r & 7) << 1)) << 4) | (h << 3));
            __nv_bfloat16 hx = __float2bfloat16(v.x), hy = __float2bfloat16(v.y);
            __nv_bfloat16 hz = __float2bfloat16(v.z), hw = __float2bfloat16(v.w);
            __nv_bfloat16 lx = __float2bfloat16(v.x - __bfloat162float(hx));
            __nv_bfloat16 ly = __float2bfloat16(v.y - __bfloat162float(hy));
            __nv_bfloat16 lz = __float2bfloat16(v.z - __bfloat162float(hz));
            __nv_bfloat16 lw = __float2bfloat16(v.w - __bfloat162float(hw));
            uint2 uh, ul;
            uh.x = ((uint32_t)*(uint16_t*)&hy << 16) | *(uint16_t*)&hx;
            uh.y = ((uint32_t)*(uint16_t*)&hw << 16) | *(uint16_t*)&hz;
            ul.x = ((uint32_t)*(uint16_t*)&ly << 16) | *(uint16_t*)&lx;
            ul.y = ((uint32_t)*(uint16_t*)&lw << 16) | *(uint16_t*)&lz;
            asm volatile("st.shared.v2.b32 [%0], {%1,%2};" :: "r"(Xhi0 + off), "r"(uh.x), "r"(uh.y) : "memory");
            asm volatile("st.shared.v2.b32 [%0], {%1,%2};" :: "r"(Xlo0 + off), "r"(ul.x), "r"(ul.y) : "memory");
        }
    }

    // Stage W chunk 0 (all 256 threads): Whi of K-half 0
    {
        const char* wsrc = (const char*)g_Wprep + wsel * 131072;  // hilo=0, half=0
        #pragma unroll
        for (int p = 0; p < 8; ++p) {
            int idx = t + p * 256;          // 0..2047 16B chunks
            asm volatile("cp.async.cg.shared.global [%0], [%1], 16;\n"
                :: "r"(Wbuf + idx * 16), "l"(wsrc + idx * 16));
        }
        asm volatile("cp.async.commit_group;\n");
        asm volatile("cp.async.wait_group 0;\n");
    }
    __syncthreads();

    // Zero linear accumulators (reuse acc)
    #pragma unroll
    for (int i = 0; i < 2; ++i)
        #pragma unroll
        for (int j = 0; j < 8; ++j)
            #pragma unroll
            for (int k = 0; k < 4; ++k) acc[i][j][k] = 0.f;

    // 4 W chunks: (hi,half0), (lo,half0), (hi,half1), (lo,half1)
    #pragma unroll 1
    for (int chunk = 0; chunk < 4; ++chunk) {
        const int half = chunk >> 1;
        const int isLo = chunk & 1;
        const int npass = isLo ? 1 : 2;
        const uint32_t abase0 = half ? Shi0 : Xhi0;
        const uint32_t abase1 = half ? Slo0 : Xlo0;

        if (warp < 4) {
            #pragma unroll 1
            for (int pass = 0; pass < npass; ++pass) {
                const uint32_t ab = pass ? abase1 : abase0;
                #pragma unroll
                for (int ks = 0; ks < 8; ++ks) {
                    uint32_t a[2][4];
                    #pragma unroll
                    for (int mt = 0; mt < 2; ++mt) {
                        int r = wm * 32 + mt * 16 + (lane & 15);
                        int c = ks * 2 + (lane >> 4);
                        uint32_t sw = r * 256 + ((c ^ ((r & 7) << 1)) << 4);
                        asm volatile("ldmatrix.sync.aligned.m8n8.x4.shared.b16 {%0,%1,%2,%3}, [%4];\n"
                            : "=r"(a[mt][0]), "=r"(a[mt][1]), "=r"(a[mt][2]), "=r"(a[mt][3])
                            : "r"(ab + sw));
                    }
                    #pragma unroll
                    for (int nt = 0; nt < 8; ++nt) {
                        uint32_t b0, b1;
                        int r = ks * 16 + (lane & 15);
                        int c = wn * 8 + nt;
                        uint32_t sw = r * 256 + ((c ^ ((r & 7) << 1)) << 4);
                        asm volatile("ldmatrix.sync.aligned.m8n8.x2.trans.shared.b16 {%0,%1}, [%2];\n"
                            : "=r"(b0), "=r"(b1) : "r"(Wbuf + sw));
                        #pragma unroll
                        for (int mt = 0; mt < 2; ++mt) {
                            asm volatile(
                                "mma.sync.aligned.m16n8k16.row.col.f32.bf16.bf16.f32 "
                                "{%0,%1,%2,%3}, {%4,%5,%6,%7}, {%8,%9}, {%0,%1,%2,%3};\n"
                                : "+f"(acc[mt][nt][0]), "+f"(acc[mt][nt][1]),
                                  "+f"(acc[mt][nt][2]), "+f"(acc[mt][nt][3])
                                : "r"(a[mt][0]), "r"(a[mt][1]), "r"(a[mt][2]), "r"(a[mt][3]),
                                  "r"(b0), "r"(b1));
                        }
                    }
                }
            }
        }
        __syncthreads();   // mma done before Wbuf overwrite
        if (chunk < 3) {
            const int nh = (chunk + 1) >> 1, nl = (chunk + 1) & 1;
            const char* wsrc = (const char*)g_Wprep + wsel * 131072 + nl * 65536 + nh * 32768;
            #pragma unroll
            for (int p = 0; p < 8; ++p) {
                int idx = t + p * 256;
                asm volatile("cp.async.cg.shared.global [%0], [%1], 16;\n"
                    :: "r"(Wbuf + idx * 16), "l"(wsrc + idx * 16));
            }
            asm volatile("cp.async.commit_group;\n");
            asm volatile("cp.async.wait_group 0;\n");
            __syncthreads();
        }
    }

    // Final write: bias + relu -> hout fp32 (+ optional bf16 g_featb)
    if (warp < 4) {
        #pragma unroll
        for (int mt = 0; mt < 2; ++mt) {
            int r0 = m0 + wm * 32 + mt * 16 + (lane >> 2);
            #pragma unroll
            for (int nt = 0; nt < 8; ++nt) {
                int c0 = wn * 64 + nt * 8 + (lane & 3) * 2;
                float bv0 = __ldg(&bias[c0]);
                float bv1 = __ldg(&bias[c0 + 1]);
                float o00 = fmaxf(acc[mt][nt][0] + bv0, 0.f);
                float o01 = fmaxf(acc[mt][nt][1] + bv1, 0.f);
                float o10 = fmaxf(acc[mt][nt][2] + bv0, 0.f);
                float o11 = fmaxf(acc[mt][nt][3] + bv1, 0.f);
                *(float2*)(hout + (size_t)r0 * FDIM + c0)       = make_float2(o00, o01);
                *(float2*)(hout + (size_t)(r0 + 8) * FDIM + c0) = make_float2(o10, o11);
                if (write_bf16) {
                    __nv_bfloat162 p0 = __float22bfloat162_rn(make_float2(o00, o01));
                    __nv_bfloat162 p1 = __float22bfloat162_rn(make_float2(o10, o11));
                    *(__nv_bfloat162*)(g_featb + (size_t)r0 * FDIM + c0)       = p0;
                    *(__nv_bfloat162*)(g_featb + (size_t)(r0 + 8) * FDIM + c0) = p1;
                }
            }
        }
    }
}

// ---------------------------------------------------------------------------
// logits = h2 @ Wl + bl ; log_probs = logits - logsumexp(logits)
// ---------------------------------------------------------------------------
__global__ void __launch_bounds__(128)
classifier_kernel(const float* __restrict__ H,
                  const float* __restrict__ Wl,
                  const float* __restrict__ bl,
                  float* __restrict__ logp,
                  float* __restrict__ logits) {
    extern __shared__ float sh[];
    float* Hs  = sh;                  // 128*129
    float* Wls = sh + 128 * 129;      // 128*40
    float* bls = Wls + 128 * NCLS;    // 40
    const int t = threadIdx.x;
    const int row0 = blockIdx.x * 128;

    for (int j = 0; j < 128; ++j)
        Hs[j * 129 + t] = H[(size_t)(row0 + j) * FDIM + t];
    for (int idx = t; idx < 128 * NCLS; idx += 128)
        Wls[idx] = Wl[idx];
    if (t < NCLS) bls[t] = bl[t];
    __syncthreads();

    float acc[NCLS];
    #pragma unroll
    for (int c = 0; c < NCLS; ++c) acc[c] = bls[c];

    const float* hr = &Hs[t * 129];
    #pragma unroll 4
    for (int k = 0; k < FDIM; ++k) {
        float xv = hr[k];
        #pragma unroll
        for (int c = 0; c < NCLS; c += 4) {
            float4 w = *(const float4*)&Wls[k * NCLS + c];
            acc[c + 0] = fmaf(xv, w.x, acc[c + 0]);
            acc[c + 1] = fmaf(xv, w.y, acc[c + 1]);
            acc[c + 2] = fmaf(xv, w.z, acc[c + 2]);
            acc[c + 3] = fmaf(xv, w.w, acc[c + 3]);
        }
    }

    float m = acc[0];
    #pragma unroll
    for (int c = 1; c < NCLS; ++c) m = fmaxf(m, acc[c]);
    float s = 0.f;
    #pragma unroll
    for (int c = 0; c < NCLS; ++c) s += __expf(acc[c] - m);
    float lse = m + __logf(s);

    size_t ro = (size_t)(row0 + t) * NCLS;
    #pragma unroll
    for (int c = 0; c < NCLS; ++c) {
        logits[ro + c] = acc[c];
        logp[ro + c]   = acc[c] - lse;
    }
}

// ---------------------------------------------------------------------------
extern "C" void kernel_launch(void* const* d_in, const int* in_sizes, int n_in,
                              void* d_out, int out_size) {
    (void)in_sizes; (void)n_in; (void)out_size;
    const float* x   = (const float*)d_in[0];
    const float* adj = (const float*)d_in[1];
    const float* W1  = (const float*)d_in[2];
    const float* b1  = (const float*)d_in[3];
    const float* W2  = (const float*)d_in[4];
    const float* b2  = (const float*)d_in[5];
    const float* Wl  = (const float*)d_in[6];
    const float* bl  = (const float*)d_in[7];

    float* out    = (float*)d_out;
    float* logp   = out;                                  // [N, 40]
    float* h1     = logp + (size_t)N_NODES * NCLS;        // [N, 128]
    float* h2     = h1 + (size_t)N_NODES * FDIM;          // [N, 128]
    float* logits = h2 + (size_t)N_NODES * FDIM;          // [N, 40]

    const int cls_smem  = (128 * 129 + 128 * NCLS + NCLS) * (int)sizeof(float);
    const int spmm_smem = STAGES * (8192 + 16384);   // 96 KB
    cudaFuncSetAttribute(spmm_fused_kernel, cudaFuncAttributeMaxDynamicSharedMemorySize, spmm_smem);
    cudaFuncSetAttribute(classifier_kernel, cudaFuncAttributeMaxDynamicSharedMemorySize, cls_smem);

    // 0) W1/W2 -> pre-swizzled bf16 hi/lo tiles
    prep_w_kernel<<<4, 256>>>(W1, W2);
    // 1) x -> bf16
    cvt_x_kernel<<<512, 256>>>(x);
    // 2) s = adj @ x ; h1 = relu([x|s]@W1+b1)  (emits bf16 h1 into g_featb)
    spmm_fused_kernel<<<N_NODES / BM, 256, spmm_smem>>>(adj, x, 0, b1, h1, 1);
    // 3) s = adj @ h1 ; h2 = relu([h1|s]@W2+b2)
    spmm_fused_kernel<<<N_NODES / BM, 256, spmm_smem>>>(adj, h1, 1, b2, h2, 0);
    // 4) logits + log_softmax
    classifier_kernel<<<N_NODES / 128, 128, cls_smem>>>(h2, Wl, bl, logp, logits);
}